// round 3
// baseline (speedup 1.0000x reference)
#include <cuda_runtime.h>
#include <cuda_bf16.h>
#include <math.h>

// ---------------- problem constants ----------------
#define NB 32          // B*T
#define D64 64
#define HH 64
#define WW 64
#define HW 4096
#define C2 128
#define BB 4
#define TT 8

// output regions (floats)
#define OUT_RE   0
#define OUT_IM   8388608
#define HOUT_RE  16777216
#define HOUT_IM  (16777216 + 1048576)
#define FLUX_RE  (16777216 + 2097152)
#define FLUX_IM  (FLUX_RE + 256)

// ---------------- packed f32x2 helpers ----------------
typedef unsigned long long u64t;
__device__ __forceinline__ u64t pk2(float lo, float hi) {
    u64t r; asm("mov.b64 %0, {%1,%2};" : "=l"(r) : "f"(lo), "f"(hi)); return r;
}
__device__ __forceinline__ u64t bcast2(float v) {
    u64t r; asm("mov.b64 %0, {%1,%1};" : "=l"(r) : "f"(v)); return r;
}
__device__ __forceinline__ void upk2(u64t v, float& lo, float& hi) {
    asm("mov.b64 {%0,%1}, %2;" : "=f"(lo), "=f"(hi) : "l"(v));
}
__device__ __forceinline__ u64t ffma2(u64t a, u64t b, u64t c) {
    u64t d; asm("fma.rn.f32x2 %0, %1, %2, %3;" : "=l"(d) : "l"(a), "l"(b), "l"(c)); return d;
}

// ---------------- scratch (device globals; no allocation) ----------------
__device__ float g_xn[NB * C2 * HW];          // layernormed, (n,c,h,w)
__device__ float g_wt[128 * 9 * 128];         // conv weights transposed: [ci][k][co]
__device__ float g_xsp_re[NB * D64 * HW];     // (n,d,h,w)
__device__ float g_xsp_im[NB * D64 * HW];
__device__ float g_xeig_re[NB * HW * D64];    // (n,h,w,e)
__device__ float g_xeig_im[NB * HW * D64];
__device__ float g_y_re[NB * HW * D64];       // (n,h,w,e)
__device__ float g_y_im[NB * HW * D64];
__device__ float g_z[NB * HW * C2];           // rows: [re(64), im(64)]
__device__ float g_sum_re[BB * TT * D64];     // 2048 (for x_mean)
__device__ float g_sum_im[BB * TT * D64];
__device__ float g_ff_re[BB * TT * D64];      // flux forcing
__device__ float g_ff_im[BB * TT * D64];
__device__ float g_gate[BB * TT * D64];
__device__ float g_src_re[BB * TT * D64];
__device__ float g_src_im[BB * TT * D64];
__device__ float g_ah_re[D64], g_ah_im[D64];
__device__ float g_ch_re[D64], g_ch_im[D64];

// ---------------- kernel 0: transpose conv weights -> [ci][k][co] ----------------
__global__ void k_wtr(const float* __restrict__ cw) {
    int idx = blockIdx.x * 256 + threadIdx.x;
    if (idx >= 128 * 9 * 128) return;
    int co = idx & 127;
    int rest = idx >> 7;
    int k = rest % 9, ci = rest / 9;
    g_wt[idx] = cw[(co * 128 + ci) * 9 + k];
}

// ---------------- kernel 1: layernorm over 128 channels ----------------
__global__ void k_ln(const float* __restrict__ xre, const float* __restrict__ xim,
                     const float* __restrict__ gamma, const float* __restrict__ beta) {
    int n = blockIdx.x >> 6, h = blockIdx.x & 63;
    int w = threadIdx.x;  // 64 threads
    if (blockIdx.x == 0) {
        for (int i = w; i < BB * TT * D64; i += 64) { g_sum_re[i] = 0.f; g_sum_im[i] = 0.f; }
    }
    int base0 = n * 262144 + h * 64 + w;   // (n, d=0, h, w); d-stride 4096
    float s = 0.f, s2 = 0.f;
    #pragma unroll 4
    for (int c = 0; c < 64; c++) { float v = xre[base0 + c * 4096]; s += v; s2 += v * v; }
    #pragma unroll 4
    for (int c = 0; c < 64; c++) { float v = xim[base0 + c * 4096]; s += v; s2 += v * v; }
    float mu  = s * (1.f / 128.f);
    float var = s2 * (1.f / 128.f) - mu * mu;
    float inv = rsqrtf(var + 1e-5f);
    int ob = n * (C2 * HW) + h * 64 + w;
    #pragma unroll 4
    for (int c = 0; c < 128; c++) {
        float v = (c < 64) ? xre[base0 + c * 4096] : xim[base0 + (c - 64) * 4096];
        g_xn[ob + c * 4096] = (v - mu) * inv * gamma[c] + beta[c];
    }
}

// ---------------- kernel 2: conv 3x3 SAME + bias + metric + residual -> xsp ----------------
// f32x2 version: weights packed along co (pairs), inputs broadcast-packed.
__global__ void __launch_bounds__(256, 2) k_conv(
        const float* __restrict__ xre, const float* __restrict__ xim,
        const float* __restrict__ cb, const float* __restrict__ metric) {
    int n = blockIdx.x >> 6, h = blockIdx.x & 63;
    int tid = threadIdx.x;
    int cog = tid >> 4;       // 16 groups * 8 co = 128
    int wg  = tid & 15;       // 16 groups * 4 w  = 64
    int w4 = wg * 4;
    __shared__ float s_in[3 * 68];
    __shared__ float s_wt[1152];      // [k(9)][co(128)]
    u64t acc2[4][4];                  // [co-pair a2][j]
    #pragma unroll
    for (int a = 0; a < 4; a++)
        #pragma unroll
        for (int j = 0; j < 4; j++) acc2[a][j] = bcast2(0.f);

    for (int ci = 0; ci < 128; ci++) {
        __syncthreads();
        for (int i = tid; i < 3 * 66; i += 256) {
            int r = i / 66, c = i % 66;
            int hh = h + r - 1, ww = c - 1;
            float v = 0.f;
            if (hh >= 0 && hh < 64 && ww >= 0 && ww < 64)
                v = g_xn[((n * 128 + ci) * 64 + hh) * 64 + ww];
            s_in[r * 68 + c] = v;
        }
        for (int i = tid; i < 1152; i += 256)
            s_wt[i] = g_wt[ci * 1152 + i];
        __syncthreads();
        u64t inb[3][6];
        #pragma unroll
        for (int r = 0; r < 3; r++)
            #pragma unroll
            for (int c = 0; c < 6; c++) inb[r][c] = bcast2(s_in[r * 68 + w4 + c]);
        #pragma unroll
        for (int a = 0; a < 4; a++) {
            int co2 = cog * 8 + a * 2;
            u64t wk[9];
            #pragma unroll
            for (int k = 0; k < 9; k++)
                wk[k] = *(const u64t*)&s_wt[k * 128 + co2];
            #pragma unroll
            for (int j = 0; j < 4; j++) {
                u64t s = acc2[a][j];
                s = ffma2(wk[0], inb[0][j],     s);
                s = ffma2(wk[1], inb[0][j + 1], s);
                s = ffma2(wk[2], inb[0][j + 2], s);
                s = ffma2(wk[3], inb[1][j],     s);
                s = ffma2(wk[4], inb[1][j + 1], s);
                s = ffma2(wk[5], inb[1][j + 2], s);
                s = ffma2(wk[6], inb[2][j],     s);
                s = ffma2(wk[7], inb[2][j + 1], s);
                s = ffma2(wk[8], inb[2][j + 2], s);
                acc2[a][j] = s;
            }
        }
    }
    #pragma unroll
    for (int a = 0; a < 4; a++) {
        int co0 = cog * 8 + a * 2;
        float b0 = cb[co0], b1 = cb[co0 + 1];
        #pragma unroll
        for (int j = 0; j < 4; j++) {
            int w = w4 + j;
            float m = metric[h * 64 + w];
            float v0, v1;
            upk2(acc2[a][j], v0, v1);
            v0 = (v0 + b0) * m;
            v1 = (v1 + b1) * m;
            // co0
            {
                int co = co0;
                if (co < 64) {
                    int idx = ((n * 64 + co) * 64 + h) * 64 + w;
                    g_xsp_re[idx] = xre[idx] + v0;
                } else {
                    int idx = ((n * 64 + (co - 64)) * 64 + h) * 64 + w;
                    g_xsp_im[idx] = xim[idx] + v0;
                }
            }
            {
                int co = co0 + 1;
                if (co < 64) {
                    int idx = ((n * 64 + co) * 64 + h) * 64 + w;
                    g_xsp_re[idx] = xre[idx] + v1;
                } else {
                    int idx = ((n * 64 + (co - 64)) * 64 + h) * 64 + w;
                    g_xsp_im[idx] = xim[idx] + v1;
                }
            }
        }
    }
}

// ---------------- kernel 3: x_eig = xsp @ E (complex) + H,W-mean partial sums ----------------
__global__ void __launch_bounds__(256) k_eig(const float* __restrict__ Er, const float* __restrict__ Ei) {
    extern __shared__ float sm[];
    float* sEr = sm;                 // 4096
    float* sEi = sEr + 4096;         // 4096
    float* sXr = sEi + 4096;         // 64*65  [d][w] padded
    float* sXi = sXr + 64 * 65;
    float* sOut = sXi + 64 * 65;     // 64*129 [w][e] padded
    int n = blockIdx.x >> 6, h = blockIdx.x & 63;
    int tid = threadIdx.x;
    int w = tid & 63;
    int eg = tid >> 6;               // 4 groups * 16 e
    for (int i = tid; i < 4096; i += 256) {
        sEr[i] = Er[i]; sEi[i] = Ei[i];
        int d = i >> 6, ww = i & 63;
        int gi = ((n * 64 + d) * 64 + h) * 64 + ww;
        sXr[d * 65 + ww] = g_xsp_re[gi];
        sXi[d * 65 + ww] = g_xsp_im[gi];
    }
    __syncthreads();
    u64t ar2[8], ai2[8];
    #pragma unroll
    for (int k = 0; k < 8; k++) { ar2[k] = bcast2(0.f); ai2[k] = bcast2(0.f); }
    int ebase = eg * 16;
    for (int d = 0; d < 64; d++) {
        float xr = sXr[d * 65 + w], xi = sXi[d * 65 + w];
        u64t xr2 = bcast2(xr), xi2 = bcast2(xi), nxi2 = bcast2(-xi);
        const u64t* er2 = (const u64t*)&sEr[d * 64 + ebase];
        const u64t* ei2 = (const u64t*)&sEi[d * 64 + ebase];
        #pragma unroll
        for (int k = 0; k < 8; k++) {
            u64t e_r = er2[k], e_i = ei2[k];
            ar2[k] = ffma2(xr2,  e_r, ar2[k]);
            ar2[k] = ffma2(nxi2, e_i, ar2[k]);
            ai2[k] = ffma2(xr2,  e_i, ai2[k]);
            ai2[k] = ffma2(xi2,  e_r, ai2[k]);
        }
    }
    float ar[16], ai[16];
    #pragma unroll
    for (int k = 0; k < 8; k++) { upk2(ar2[k], ar[2 * k], ar[2 * k + 1]); upk2(ai2[k], ai[2 * k], ai[2 * k + 1]); }
    // mean partial: reduce over w within each warp, then atomic
    #pragma unroll
    for (int k = 0; k < 16; k++) {
        float sr = ar[k], si = ai[k];
        #pragma unroll
        for (int off = 16; off > 0; off >>= 1) {
            sr += __shfl_xor_sync(0xffffffff, sr, off);
            si += __shfl_xor_sync(0xffffffff, si, off);
        }
        if ((tid & 31) == 0) {
            atomicAdd(&g_sum_re[n * 64 + ebase + k], sr);
            atomicAdd(&g_sum_im[n * 64 + ebase + k], si);
        }
    }
    int base = (n * 64 + h) * 4096;
    #pragma unroll
    for (int k = 0; k < 16; k++) sOut[w * 129 + ebase + k] = ar[k];
    __syncthreads();
    for (int i = tid; i < 4096; i += 256) g_xeig_re[base + i] = sOut[(i >> 6) * 129 + (i & 63)];
    __syncthreads();
    #pragma unroll
    for (int k = 0; k < 16; k++) sOut[w * 129 + ebase + k] = ai[k];
    __syncthreads();
    for (int i = tid; i < 4096; i += 256) g_xeig_im[base + i] = sOut[(i >> 6) * 129 + (i & 63)];
}

// ---------------- kernel 4a: flux recurrence + a_h/c_h (single small block) ----------------
__global__ void k_flux1(const float* __restrict__ dtp,
                        const float* __restrict__ lfre, const float* __restrict__ lfim,
                        const float* __restrict__ lhre, const float* __restrict__ lhim,
                        const float* __restrict__ fpre, const float* __restrict__ fpim,
                        float* __restrict__ out) {
    int tid = threadIdx.x;           // 256
    int b = tid >> 6, d = tid & 63;
    float dtv = dtp[0];
    float lfr = -fabsf(lfre[d]), lfi = lfim[d];
    float efac = expf(lfr * dtv);
    float afr = efac * cosf(lfi * dtv), afi = efac * sinf(lfi * dtv);
    float den = lfr * lfr + lfi * lfi;
    float nr = afr - 1.f, ni = afi;
    float cfr = (nr * lfr + ni * lfi) / den;
    float cfi = (ni * lfr - nr * lfi) / den;
    float fr = fpre[b * 64 + d], fi = fpim[b * 64 + d];
    for (int t = 0; t < TT; t++) {
        g_ff_re[(b * TT + t) * 64 + d] = fr;
        g_ff_im[(b * TT + t) * 64 + d] = fi;
        float xmr = g_sum_re[(b * TT + t) * 64 + d] * (1.f / 4096.f);
        float xmi = g_sum_im[(b * TT + t) * 64 + d] * (1.f / 4096.f);
        float ur = xmr * cfr - xmi * cfi;
        float ui = xmr * cfi + xmi * cfr;
        float nfr = afr * fr - afi * fi + ur;
        float nfi = afr * fi + afi * fr + ui;
        fr = nfr; fi = nfi;
    }
    out[FLUX_RE + b * 64 + d] = fr;
    out[FLUX_IM + b * 64 + d] = fi;

    if (tid < 64) {
        float lr = -fabsf(lhre[tid]), li = lhim[tid];
        float e2 = expf(lr * dtv);
        float ahr = e2 * cosf(li * dtv), ahi = e2 * sinf(li * dtv);
        float dd = lr * lr + li * li;
        float mr = ahr - 1.f, mi = ahi;
        g_ah_re[tid] = ahr; g_ah_im[tid] = ahi;
        g_ch_re[tid] = (mr * lr + mi * li) / dd;
        g_ch_im[tid] = (mi * lr - mr * li) / dd;
    }
}

// ---------------- kernel 4b: source & gate (parallel over b*t blocks) ----------------
__global__ void k_flux2(const float* __restrict__ Wsr, const float* __restrict__ Wsi,
                        const float* __restrict__ Wg,  const float* __restrict__ bg) {
    int blk = blockIdx.x;            // 32 = B*T
    int e = threadIdx.x;             // 64
    __shared__ float sfr[64], sfi[64];
    sfr[e] = g_ff_re[blk * 64 + e];
    sfi[e] = g_ff_im[blk * 64 + e];
    __syncthreads();
    float sr = 0.f, si = 0.f, ga = bg[e];
    #pragma unroll 4
    for (int dd = 0; dd < 64; dd++) {
        float ffr = sfr[dd], ffi = sfi[dd];
        float wr = Wsr[dd * 64 + e], wi = Wsi[dd * 64 + e];
        sr += ffr * wr - ffi * wi;
        si += ffr * wi + ffi * wr;
        ga += ffr * Wg[dd * 64 + e];
    }
    int q = blk * 64 + e;
    g_src_re[q] = sr;
    g_src_im[q] = si;
    g_gate[q] = 1.f / (1.f + expf(-ga));
}

// ---------------- kernel 5: T-scan for y + h_out ----------------
__global__ void k_scan(const float* __restrict__ hpr, const float* __restrict__ hpi,
                       float* __restrict__ out) {
    int gid = blockIdx.x * 256 + threadIdx.x;    // 1048576 threads
    int e = gid & 63;
    int pos = gid >> 6;                          // b*4096 + hw
    int b = pos >> 12, hw = pos & 4095;
    float ahr = g_ah_re[e], ahi = g_ah_im[e];
    float chr = g_ch_re[e], chi = g_ch_im[e];
    float yr = hpr[gid], yi = hpi[gid];
    #pragma unroll
    for (int t = 0; t < TT; t++) {
        int idx = ((b * TT + t) * 4096 + hw) * 64 + e;
        float xr = g_xeig_re[idx], xi = g_xeig_im[idx];
        int q = (b * TT + t) * 64 + e;
        float gg = g_gate[q];
        float sr = g_src_re[q], si = g_src_im[q];
        float fr = xr * gg + sr * (1.f - gg);
        float fi = xi * gg + si * (1.f - gg);
        float ur = fr * chr - fi * chi;
        float ui = fr * chi + fi * chr;
        float nyr = ahr * yr - ahi * yi + ur;
        float nyi = ahr * yi + ahi * yr + ui;
        yr = nyr; yi = nyi;
        g_y_re[idx] = yr; g_y_im[idx] = yi;
    }
    out[HOUT_RE + gid] = yr;
    out[HOUT_IM + gid] = yi;
}

// ---------------- kernel 6: y_dec = y @ Edec (complex) -> z rows ----------------
__global__ void __launch_bounds__(256) k_dec(const float* __restrict__ Er, const float* __restrict__ Ei) {
    extern __shared__ float sm[];
    float* sEr = sm;
    float* sEi = sEr + 4096;
    float* sYr = sEi + 4096;          // [w][d] padded 65
    float* sYi = sYr + 64 * 65;
    float* sOut = sYi + 64 * 65;      // [w][c] padded 129
    int n = blockIdx.x >> 6, h = blockIdx.x & 63;
    int tid = threadIdx.x;
    int w = tid & 63;
    int eg = tid >> 6;
    int base = (n * 64 + h) * 4096;
    for (int i = tid; i < 4096; i += 256) {
        sEr[i] = Er[i]; sEi[i] = Ei[i];
        sYr[(i >> 6) * 65 + (i & 63)] = g_y_re[base + i];
        sYi[(i >> 6) * 65 + (i & 63)] = g_y_im[base + i];
    }
    __syncthreads();
    u64t ar2[8], ai2[8];
    #pragma unroll
    for (int k = 0; k < 8; k++) { ar2[k] = bcast2(0.f); ai2[k] = bcast2(0.f); }
    int ebase = eg * 16;
    for (int d = 0; d < 64; d++) {
        float xr = sYr[w * 65 + d], xi = sYi[w * 65 + d];
        u64t xr2 = bcast2(xr), xi2 = bcast2(xi), nxi2 = bcast2(-xi);
        const u64t* er2 = (const u64t*)&sEr[d * 64 + ebase];
        const u64t* ei2 = (const u64t*)&sEi[d * 64 + ebase];
        #pragma unroll
        for (int k = 0; k < 8; k++) {
            u64t e_r = er2[k], e_i = ei2[k];
            ar2[k] = ffma2(xr2,  e_r, ar2[k]);
            ar2[k] = ffma2(nxi2, e_i, ar2[k]);
            ai2[k] = ffma2(xr2,  e_i, ai2[k]);
            ai2[k] = ffma2(xi2,  e_r, ai2[k]);
        }
    }
    float ar[16], ai[16];
    #pragma unroll
    for (int k = 0; k < 8; k++) { upk2(ar2[k], ar[2 * k], ar[2 * k + 1]); upk2(ai2[k], ai[2 * k], ai[2 * k + 1]); }
    #pragma unroll
    for (int k = 0; k < 16; k++) {
        sOut[w * 129 + ebase + k] = ar[k];
        sOut[w * 129 + 64 + ebase + k] = ai[k];
    }
    __syncthreads();
    int zb = (n * 64 + h) * 8192;
    for (int i = tid; i < 8192; i += 256)
        g_z[zb + i] = sOut[(i >> 7) * 129 + (i & 127)];
}

// ---------------- kernel 7: fused FFN + final residual output (f32x2) ----------------
__global__ void __launch_bounds__(256) k_ffn(const float* __restrict__ w1, const float* __restrict__ b1,
                                             const float* __restrict__ w2, const float* __restrict__ b2,
                                             float* __restrict__ out) {
    extern __shared__ float sm[];
    float* zs  = sm;                  // 32*129 rows [r][c]
    float* w1s = zs + 32 * 129;       // 128*64   [k][j]
    float* hid = w1s + 8192;          // 32*64    [r][j]
    float* w2s = hid + 2048;          // 64*128   [k][c]
    float* ob  = w2s + 8192;          // 128*33   [c][r]
    int blk = blockIdx.x;             // 4096
    int half = blk & 1;
    int nh = blk >> 1;
    int n = nh >> 6, h = nh & 63;
    int w0 = half * 32;
    int tid = threadIdx.x;
    int rowbase = (n * 64 + h) * 64 + w0;

    for (int i = tid; i < 32 * 128; i += 256)
        zs[(i >> 7) * 129 + (i & 127)] = g_z[(rowbase + (i >> 7)) * 128 + (i & 127)];

    // phase1 mapping: 1 row per thread, 8 j's (4 pairs)
    int rg = tid >> 3;                // 0..31
    int jg = tid & 7;                 // j base = jg*8
    // phase2 mapping: 2 rows, 8 c's (4 pairs)
    int rg2 = tid >> 4;               // 0..15 -> rows 2rg2, 2rg2+1
    int cg = tid & 15;                // c base = cg*8
    u64t acc2[2][4];
    #pragma unroll
    for (int a = 0; a < 2; a++)
        #pragma unroll
        for (int c = 0; c < 4; c++) acc2[a][c] = bcast2(0.f);

    for (int hc = 0; hc < 8; hc++) {
        __syncthreads();
        for (int i = tid; i < 8192; i += 256)
            w1s[i] = w1[(i >> 6) * 512 + hc * 64 + (i & 63)];
        for (int i = tid; i < 8192; i += 256)
            w2s[i] = w2[(hc * 64 + (i >> 7)) * 128 + (i & 127)];
        __syncthreads();

        u64t hv2[4];
        #pragma unroll
        for (int jj = 0; jj < 4; jj++) hv2[jj] = bcast2(0.f);
        const float* zrow = &zs[rg * 129];
        for (int k = 0; k < 128; k++) {
            u64t zb2 = bcast2(zrow[k]);
            const u64t* wp = (const u64t*)&w1s[k * 64 + jg * 8];
            #pragma unroll
            for (int jj = 0; jj < 4; jj++)
                hv2[jj] = ffma2(zb2, wp[jj], hv2[jj]);
        }
        #pragma unroll
        for (int jj = 0; jj < 4; jj++) {
            float v0, v1;
            upk2(hv2[jj], v0, v1);
            int j0 = jg * 8 + jj * 2;
            float x0 = v0 + b1[hc * 64 + j0];
            float x1 = v1 + b1[hc * 64 + j0 + 1];
            float t0 = tanhf(0.7978845608028654f * (x0 + 0.044715f * x0 * x0 * x0));
            float t1 = tanhf(0.7978845608028654f * (x1 + 0.044715f * x1 * x1 * x1));
            hid[rg * 64 + j0]     = 0.5f * x0 * (1.f + t0);
            hid[rg * 64 + j0 + 1] = 0.5f * x1 * (1.f + t1);
        }
        __syncthreads();
        for (int k = 0; k < 64; k++) {
            u64t h0 = bcast2(hid[(2 * rg2) * 64 + k]);
            u64t h1 = bcast2(hid[(2 * rg2 + 1) * 64 + k]);
            const u64t* wp = (const u64t*)&w2s[k * 128 + cg * 8];
            #pragma unroll
            for (int cc = 0; cc < 4; cc++) {
                acc2[0][cc] = ffma2(h0, wp[cc], acc2[0][cc]);
                acc2[1][cc] = ffma2(h1, wp[cc], acc2[1][cc]);
            }
        }
    }
    __syncthreads();
    #pragma unroll
    for (int rr = 0; rr < 2; rr++)
        #pragma unroll
        for (int cc = 0; cc < 4; cc++) {
            float v0, v1;
            upk2(acc2[rr][cc], v0, v1);
            int c0 = cg * 8 + cc * 2;
            int row = 2 * rg2 + rr;
            ob[c0 * 33 + row]       = v0;
            ob[(c0 + 1) * 33 + row] = v1;
        }
    __syncthreads();
    for (int i = tid; i < 4096; i += 256) {
        int c = i >> 5, w = i & 31;
        float o = ob[c * 33 + w] + b2[c];
        float zv = zs[w * 129 + c];
        int d = c & 63;
        int gidx = ((n * 64 + d) * 64 + h) * 64 + w0 + w;
        if (c < 64) out[OUT_RE + gidx] = g_xsp_re[gidx] + zv + o;
        else        out[OUT_IM + gidx] = g_xsp_im[gidx] + zv + o;
    }
}

// ---------------- launch ----------------
extern "C" void kernel_launch(void* const* d_in, const int* in_sizes, int n_in,
                              void* d_out, int out_size) {
    const float* x_re      = (const float*)d_in[0];
    const float* x_im      = (const float*)d_in[1];
    const float* h_prev_re = (const float*)d_in[2];
    const float* h_prev_im = (const float*)d_in[3];
    const float* flux_p_re = (const float*)d_in[4];
    const float* flux_p_im = (const float*)d_in[5];
    const float* dt        = (const float*)d_in[6];
    const float* ln_gamma  = (const float*)d_in[7];
    const float* ln_beta   = (const float*)d_in[8];
    const float* conv_w    = (const float*)d_in[9];
    const float* conv_b    = (const float*)d_in[10];
    const float* metric    = (const float*)d_in[11];
    const float* E_re      = (const float*)d_in[12];
    const float* E_im      = (const float*)d_in[13];
    const float* Edec_re   = (const float*)d_in[14];
    const float* Edec_im   = (const float*)d_in[15];
    const float* lam_h_re  = (const float*)d_in[16];
    const float* lam_h_im  = (const float*)d_in[17];
    const float* lam_f_re  = (const float*)d_in[18];
    const float* lam_f_im  = (const float*)d_in[19];
    const float* W_src_re  = (const float*)d_in[20];
    const float* W_src_im  = (const float*)d_in[21];
    const float* W_gate    = (const float*)d_in[22];
    const float* b_gate    = (const float*)d_in[23];
    const float* ffn_w1    = (const float*)d_in[24];
    const float* ffn_b1    = (const float*)d_in[25];
    const float* ffn_w2    = (const float*)d_in[26];
    const float* ffn_b2    = (const float*)d_in[27];
    float* out = (float*)d_out;

    const int smem_eig = (4096 * 2 + 64 * 65 * 2 + 64 * 129) * 4;   // 99072
    const int smem_ffn = (32 * 129 + 8192 + 2048 + 8192 + 128 * 33) * 4;  // 107136
    cudaFuncSetAttribute(k_eig, cudaFuncAttributeMaxDynamicSharedMemorySize, smem_eig);
    cudaFuncSetAttribute(k_dec, cudaFuncAttributeMaxDynamicSharedMemorySize, smem_eig);
    cudaFuncSetAttribute(k_ffn, cudaFuncAttributeMaxDynamicSharedMemorySize, smem_ffn);

    k_wtr <<<(128 * 9 * 128 + 255) / 256, 256>>>(conv_w);
    k_ln  <<<NB * HH, 64>>>(x_re, x_im, ln_gamma, ln_beta);
    k_conv<<<NB * HH, 256>>>(x_re, x_im, conv_b, metric);
    k_eig <<<NB * HH, 256, smem_eig>>>(E_re, E_im);
    k_flux1<<<1, 256>>>(dt, lam_f_re, lam_f_im, lam_h_re, lam_h_im,
                        flux_p_re, flux_p_im, out);
    k_flux2<<<32, 64>>>(W_src_re, W_src_im, W_gate, b_gate);
    k_scan<<<4096, 256>>>(h_prev_re, h_prev_im, out);
    k_dec <<<NB * HH, 256, smem_eig>>>(Edec_re, Edec_im);
    k_ffn <<<NB * HH * 2, 256, smem_ffn>>>(ffn_w1, ffn_b1, ffn_w2, ffn_b2, out);
}

// round 10
// speedup vs baseline: 1.8979x; 1.8979x over previous
#include <cuda_runtime.h>
#include <cuda_bf16.h>
#include <math.h>

// ---------------- problem constants ----------------
#define NB 32          // B*T
#define D64 64
#define HH 64
#define WW 64
#define HW 4096
#define C2 128
#define BB 4
#define TT 8

// output regions (floats)
#define OUT_RE   0
#define OUT_IM   8388608
#define HOUT_RE  16777216
#define HOUT_IM  (16777216 + 1048576)
#define FLUX_RE  (16777216 + 2097152)
#define FLUX_IM  (FLUX_RE + 256)

// ---------------- scratch (device globals; no allocation) ----------------
__device__ float g_xn[NB * C2 * HW];          // layernormed, (n,c,h,w)
__device__ float g_xsp_re[NB * D64 * HW];     // (n,d,h,w)
__device__ float g_xsp_im[NB * D64 * HW];
__device__ float g_xeig_re[NB * HW * D64];    // (n,h,w,e)
__device__ float g_xeig_im[NB * HW * D64];
__device__ float g_y_re[NB * HW * D64];       // (n,h,w,e)
__device__ float g_y_im[NB * HW * D64];
__device__ float g_z[NB * HW * C2];           // rows: [re(64), im(64)]
__device__ float g_sum_re[BB * TT * D64];     // 2048 (for x_mean)
__device__ float g_sum_im[BB * TT * D64];
__device__ float g_ff_re[BB * TT * D64];      // flux forcing
__device__ float g_ff_im[BB * TT * D64];
__device__ float g_gate[BB * TT * D64];
__device__ float g_src_re[BB * TT * D64];
__device__ float g_src_im[BB * TT * D64];
__device__ float g_ah_re[D64], g_ah_im[D64];
__device__ float g_ch_re[D64], g_ch_im[D64];

// ---------------- tf32 helpers ----------------
__device__ __forceinline__ float tf32r(float x) {
    float y; asm("cvt.rna.tf32.f32 %0, %1;" : "=f"(y) : "f"(x)); return y;
}
__device__ __forceinline__ void mma_tf32(float* c, float a0, float a1, float a2, float a3,
                                         float b0, float b1) {
    asm volatile("mma.sync.aligned.m16n8k8.row.col.f32.tf32.tf32.f32 "
        "{%0,%1,%2,%3}, {%4,%5,%6,%7}, {%8,%9}, {%0,%1,%2,%3};"
        : "+f"(c[0]), "+f"(c[1]), "+f"(c[2]), "+f"(c[3])
        : "r"(__float_as_uint(a0)), "r"(__float_as_uint(a1)),
          "r"(__float_as_uint(a2)), "r"(__float_as_uint(a3)),
          "r"(__float_as_uint(b0)), "r"(__float_as_uint(b1)));
}

// ---------------- kernel 1: layernorm over 128 channels ----------------
__global__ void k_ln(const float* __restrict__ xre, const float* __restrict__ xim,
                     const float* __restrict__ gamma, const float* __restrict__ beta) {
    int n = blockIdx.x >> 6, h = blockIdx.x & 63;
    int w = threadIdx.x;  // 64 threads
    if (blockIdx.x == 0) {
        for (int i = w; i < BB * TT * D64; i += 64) { g_sum_re[i] = 0.f; g_sum_im[i] = 0.f; }
    }
    int base0 = n * 262144 + h * 64 + w;   // (n, d=0, h, w); d-stride 4096
    float s = 0.f, s2 = 0.f;
    #pragma unroll 4
    for (int c = 0; c < 64; c++) { float v = xre[base0 + c * 4096]; s += v; s2 += v * v; }
    #pragma unroll 4
    for (int c = 0; c < 64; c++) { float v = xim[base0 + c * 4096]; s += v; s2 += v * v; }
    float mu  = s * (1.f / 128.f);
    float var = s2 * (1.f / 128.f) - mu * mu;
    float inv = rsqrtf(var + 1e-5f);
    int ob = n * (C2 * HW) + h * 64 + w;
    #pragma unroll 4
    for (int c = 0; c < 128; c++) {
        float v = (c < 64) ? xre[base0 + c * 4096] : xim[base0 + (c - 64) * 4096];
        g_xn[ob + c * 4096] = (v - mu) * inv * gamma[c] + beta[c];
    }
}

// ---------------- kernel 2: conv 3x3 SAME + bias + metric + residual -> xsp (scalar R1) ----------------
__global__ void __launch_bounds__(256) k_conv(
        const float* __restrict__ xre, const float* __restrict__ xim,
        const float* __restrict__ cw, const float* __restrict__ cb,
        const float* __restrict__ metric) {
    int n = blockIdx.x >> 6, h = blockIdx.x & 63;
    int tid = threadIdx.x;
    int cog = tid >> 4;       // 16 groups * 8 co = 128
    int wg  = tid & 15;       // 16 groups * 4 w  = 64
    int w4 = wg * 4;
    __shared__ float s_in[3 * 68];
    __shared__ float s_wt[1152];
    float acc[8][4];
    #pragma unroll
    for (int a = 0; a < 8; a++)
        #pragma unroll
        for (int j = 0; j < 4; j++) acc[a][j] = 0.f;

    for (int ci = 0; ci < 128; ci++) {
        __syncthreads();
        for (int i = tid; i < 3 * 66; i += 256) {
            int r = i / 66, c = i % 66;
            int hh = h + r - 1, ww = c - 1;
            float v = 0.f;
            if (hh >= 0 && hh < 64 && ww >= 0 && ww < 64)
                v = g_xn[((n * 128 + ci) * 64 + hh) * 64 + ww];
            s_in[r * 68 + c] = v;
        }
        for (int i = tid; i < 1152; i += 256) {
            int co = i / 9, k = i % 9;
            s_wt[i] = cw[(co * 128 + ci) * 9 + k];
        }
        __syncthreads();
        float in[3][6];
        #pragma unroll
        for (int r = 0; r < 3; r++)
            #pragma unroll
            for (int c = 0; c < 6; c++) in[r][c] = s_in[r * 68 + w4 + c];
        #pragma unroll
        for (int a = 0; a < 8; a++) {
            const float* wp = &s_wt[(cog * 8 + a) * 9];
            float w00 = wp[0], w01 = wp[1], w02 = wp[2];
            float w10 = wp[3], w11 = wp[4], w12 = wp[5];
            float w20 = wp[6], w21 = wp[7], w22 = wp[8];
            #pragma unroll
            for (int j = 0; j < 4; j++) {
                acc[a][j] += w00 * in[0][j] + w01 * in[0][j + 1] + w02 * in[0][j + 2]
                           + w10 * in[1][j] + w11 * in[1][j + 1] + w12 * in[1][j + 2]
                           + w20 * in[2][j] + w21 * in[2][j + 1] + w22 * in[2][j + 2];
            }
        }
    }
    #pragma unroll
    for (int a = 0; a < 8; a++) {
        int co = cog * 8 + a;
        float bias = cb[co];
        #pragma unroll
        for (int j = 0; j < 4; j++) {
            int w = w4 + j;
            float val = (acc[a][j] + bias) * metric[h * 64 + w];
            if (co < 64) {
                int idx = ((n * 64 + co) * 64 + h) * 64 + w;
                g_xsp_re[idx] = xre[idx] + val;
            } else {
                int idx = ((n * 64 + (co - 64)) * 64 + h) * 64 + w;
                g_xsp_im[idx] = xim[idx] + val;
            }
        }
    }
}

// ---------------- kernel 3: x_eig = xsp @ E (complex) + H,W-mean partial sums (scalar R1) ----------------
__global__ void __launch_bounds__(256) k_eig(const float* __restrict__ Er, const float* __restrict__ Ei) {
    extern __shared__ float sm[];
    float* sEr = sm;                 // 4096
    float* sEi = sEr + 4096;         // 4096
    float* sXr = sEi + 4096;         // 64*65  [d][w] padded
    float* sXi = sXr + 64 * 65;
    float* sOut = sXi + 64 * 65;     // 64*129 [w][e] padded
    int n = blockIdx.x >> 6, h = blockIdx.x & 63;
    int tid = threadIdx.x;
    int w = tid & 63;
    int eg = tid >> 6;               // 4 groups * 16 e
    for (int i = tid; i < 4096; i += 256) {
        sEr[i] = Er[i]; sEi[i] = Ei[i];
        int d = i >> 6, ww = i & 63;
        int gi = ((n * 64 + d) * 64 + h) * 64 + ww;
        sXr[d * 65 + ww] = g_xsp_re[gi];
        sXi[d * 65 + ww] = g_xsp_im[gi];
    }
    __syncthreads();
    float ar[16], ai[16];
    #pragma unroll
    for (int k = 0; k < 16; k++) { ar[k] = 0.f; ai[k] = 0.f; }
    for (int d = 0; d < 64; d++) {
        float xr = sXr[d * 65 + w], xi = sXi[d * 65 + w];
        #pragma unroll
        for (int k = 0; k < 16; k++) {
            int e = eg * 16 + k;
            float er = sEr[d * 64 + e], ei = sEi[d * 64 + e];
            ar[k] += xr * er - xi * ei;
            ai[k] += xr * ei + xi * er;
        }
    }
    #pragma unroll
    for (int k = 0; k < 16; k++) {
        float sr = ar[k], si = ai[k];
        #pragma unroll
        for (int off = 16; off > 0; off >>= 1) {
            sr += __shfl_xor_sync(0xffffffff, sr, off);
            si += __shfl_xor_sync(0xffffffff, si, off);
        }
        if ((tid & 31) == 0) {
            atomicAdd(&g_sum_re[n * 64 + eg * 16 + k], sr);
            atomicAdd(&g_sum_im[n * 64 + eg * 16 + k], si);
        }
    }
    int base = (n * 64 + h) * 4096;
    #pragma unroll
    for (int k = 0; k < 16; k++) sOut[w * 129 + eg * 16 + k] = ar[k];
    __syncthreads();
    for (int i = tid; i < 4096; i += 256) g_xeig_re[base + i] = sOut[(i >> 6) * 129 + (i & 63)];
    __syncthreads();
    #pragma unroll
    for (int k = 0; k < 16; k++) sOut[w * 129 + eg * 16 + k] = ai[k];
    __syncthreads();
    for (int i = tid; i < 4096; i += 256) g_xeig_im[base + i] = sOut[(i >> 6) * 129 + (i & 63)];
}

// ---------------- kernel 4a: flux recurrence + a_h/c_h ----------------
__global__ void k_flux1(const float* __restrict__ dtp,
                        const float* __restrict__ lfre, const float* __restrict__ lfim,
                        const float* __restrict__ lhre, const float* __restrict__ lhim,
                        const float* __restrict__ fpre, const float* __restrict__ fpim,
                        float* __restrict__ out) {
    int tid = threadIdx.x;           // 256
    int b = tid >> 6, d = tid & 63;
    float dtv = dtp[0];
    float lfr = -fabsf(lfre[d]), lfi = lfim[d];
    float efac = expf(lfr * dtv);
    float afr = efac * cosf(lfi * dtv), afi = efac * sinf(lfi * dtv);
    float den = lfr * lfr + lfi * lfi;
    float nr = afr - 1.f, ni = afi;
    float cfr = (nr * lfr + ni * lfi) / den;
    float cfi = (ni * lfr - nr * lfi) / den;
    float fr = fpre[b * 64 + d], fi = fpim[b * 64 + d];
    for (int t = 0; t < TT; t++) {
        g_ff_re[(b * TT + t) * 64 + d] = fr;
        g_ff_im[(b * TT + t) * 64 + d] = fi;
        float xmr = g_sum_re[(b * TT + t) * 64 + d] * (1.f / 4096.f);
        float xmi = g_sum_im[(b * TT + t) * 64 + d] * (1.f / 4096.f);
        float ur = xmr * cfr - xmi * cfi;
        float ui = xmr * cfi + xmi * cfr;
        float nfr = afr * fr - afi * fi + ur;
        float nfi = afr * fi + afi * fr + ui;
        fr = nfr; fi = nfi;
    }
    out[FLUX_RE + b * 64 + d] = fr;
    out[FLUX_IM + b * 64 + d] = fi;

    if (tid < 64) {
        float lr = -fabsf(lhre[tid]), li = lhim[tid];
        float e2 = expf(lr * dtv);
        float ahr = e2 * cosf(li * dtv), ahi = e2 * sinf(li * dtv);
        float dd = lr * lr + li * li;
        float mr = ahr - 1.f, mi = ahi;
        g_ah_re[tid] = ahr; g_ah_im[tid] = ahi;
        g_ch_re[tid] = (mr * lr + mi * li) / dd;
        g_ch_im[tid] = (mi * lr - mr * li) / dd;
    }
}

// ---------------- kernel 4b: source & gate ----------------
__global__ void k_flux2(const float* __restrict__ Wsr, const float* __restrict__ Wsi,
                        const float* __restrict__ Wg,  const float* __restrict__ bg) {
    int blk = blockIdx.x;            // 32 = B*T
    int e = threadIdx.x;             // 64
    __shared__ float sfr[64], sfi[64];
    sfr[e] = g_ff_re[blk * 64 + e];
    sfi[e] = g_ff_im[blk * 64 + e];
    __syncthreads();
    float sr = 0.f, si = 0.f, ga = bg[e];
    #pragma unroll 4
    for (int dd = 0; dd < 64; dd++) {
        float ffr = sfr[dd], ffi = sfi[dd];
        float wr = Wsr[dd * 64 + e], wi = Wsi[dd * 64 + e];
        sr += ffr * wr - ffi * wi;
        si += ffr * wi + ffi * wr;
        ga += ffr * Wg[dd * 64 + e];
    }
    int q = blk * 64 + e;
    g_src_re[q] = sr;
    g_src_im[q] = si;
    g_gate[q] = 1.f / (1.f + expf(-ga));
}

// ---------------- kernel 5: T-scan for y + h_out ----------------
__global__ void k_scan(const float* __restrict__ hpr, const float* __restrict__ hpi,
                       float* __restrict__ out) {
    int gid = blockIdx.x * 256 + threadIdx.x;    // 1048576 threads
    int e = gid & 63;
    int pos = gid >> 6;                          // b*4096 + hw
    int b = pos >> 12, hw = pos & 4095;
    float ahr = g_ah_re[e], ahi = g_ah_im[e];
    float chr = g_ch_re[e], chi = g_ch_im[e];
    float yr = hpr[gid], yi = hpi[gid];
    #pragma unroll
    for (int t = 0; t < TT; t++) {
        int idx = ((b * TT + t) * 4096 + hw) * 64 + e;
        float xr = g_xeig_re[idx], xi = g_xeig_im[idx];
        int q = (b * TT + t) * 64 + e;
        float gg = g_gate[q];
        float sr = g_src_re[q], si = g_src_im[q];
        float fr = xr * gg + sr * (1.f - gg);
        float fi = xi * gg + si * (1.f - gg);
        float ur = fr * chr - fi * chi;
        float ui = fr * chi + fi * chr;
        float nyr = ahr * yr - ahi * yi + ur;
        float nyi = ahr * yi + ahi * yr + ui;
        yr = nyr; yi = nyi;
        g_y_re[idx] = yr; g_y_im[idx] = yi;
    }
    out[HOUT_RE + gid] = yr;
    out[HOUT_IM + gid] = yi;
}

// ---------------- kernel 6: y_dec = y @ Edec (complex) -> z rows (scalar R1) ----------------
__global__ void __launch_bounds__(256) k_dec(const float* __restrict__ Er, const float* __restrict__ Ei) {
    extern __shared__ float sm[];
    float* sEr = sm;
    float* sEi = sEr + 4096;
    float* sYr = sEi + 4096;          // [w][d] padded 65
    float* sYi = sYr + 64 * 65;
    float* sOut = sYi + 64 * 65;      // [w][c] padded 129
    int n = blockIdx.x >> 6, h = blockIdx.x & 63;
    int tid = threadIdx.x;
    int w = tid & 63;
    int eg = tid >> 6;
    int base = (n * 64 + h) * 4096;
    for (int i = tid; i < 4096; i += 256) {
        sEr[i] = Er[i]; sEi[i] = Ei[i];
        sYr[(i >> 6) * 65 + (i & 63)] = g_y_re[base + i];
        sYi[(i >> 6) * 65 + (i & 63)] = g_y_im[base + i];
    }
    __syncthreads();
    float ar[16], ai[16];
    #pragma unroll
    for (int k = 0; k < 16; k++) { ar[k] = 0.f; ai[k] = 0.f; }
    for (int d = 0; d < 64; d++) {
        float xr = sYr[w * 65 + d], xi = sYi[w * 65 + d];
        #pragma unroll
        for (int k = 0; k < 16; k++) {
            int e = eg * 16 + k;
            float er = sEr[d * 64 + e], ei = sEi[d * 64 + e];
            ar[k] += xr * er - xi * ei;
            ai[k] += xr * ei + xi * er;
        }
    }
    #pragma unroll
    for (int k = 0; k < 16; k++) {
        sOut[w * 129 + eg * 16 + k] = ar[k];
        sOut[w * 129 + 64 + eg * 16 + k] = ai[k];
    }
    __syncthreads();
    int zb = (n * 64 + h) * 8192;
    for (int i = tid; i < 8192; i += 256)
        g_z[zb + i] = sOut[(i >> 7) * 129 + (i & 127)];
}

// ---------------- kernel 7: fused FFN via tf32 mma.sync + final residual ----------------
// One block per (n,h): 64 rows (w), 128 -> 512 (gelu) -> 128, hidden chunked by 64.
// 8 warps, warp grid 4x2: wm = warp>>1 (rows wm*16..), wn = warp&1.
// Residual xsp read via device globals INSIDE the kernel (host cannot pass
// __device__ symbol addresses as arguments — that was the R6 bug).
__global__ void __launch_bounds__(256) k_ffn(const float* __restrict__ w1, const float* __restrict__ b1,
                                             const float* __restrict__ w2, const float* __restrict__ b2,
                                             float* __restrict__ out) {
    extern __shared__ float sm[];
    float* zs = sm;                   // 64 x 132  (rows x cols, fp32 exact)
    float* wb = zs + 64 * 132;        // 9216 floats: W1 chunk [128][72] / W2 chunk [64][136] / ob [128][66]
    float* hd = wb + 9216;            // 64 x 72   hidden chunk (tf32-rounded)
    int blk = blockIdx.x;             // 2048
    int n = blk >> 6, h = blk & 63;
    int tid = threadIdx.x;
    int lane = tid & 31, warp = tid >> 5;
    int wm = warp >> 1, wn = warp & 1;
    int rowb = wm * 16;
    int lg = lane >> 2;               // groupID 0..7
    int lt = lane & 3;                // threadInGroup 0..3
    int rowbase = (n * 64 + h) * 64;  // global z row base

    for (int i = tid; i < 8192; i += 256)
        zs[(i >> 7) * 132 + (i & 127)] = g_z[(rowbase + (i >> 7)) * 128 + (i & 127)];

    float c2[8][4];
    #pragma unroll
    for (int a = 0; a < 8; a++)
        #pragma unroll
        for (int q = 0; q < 4; q++) c2[a][q] = 0.f;

    for (int hc = 0; hc < 8; hc++) {
        __syncthreads();
        // stage W1 chunk [k 128][j 64] -> wb stride 72 (tf32-rounded)
        for (int i = tid; i < 8192; i += 256) {
            int k = i >> 6, j = i & 63;
            wb[k * 72 + j] = tf32r(w1[k * 512 + hc * 64 + j]);
        }
        __syncthreads();
        // GEMM1: c1[64 rows x 64 chunk-cols]; per warp m16 x n32, k=128
        float c1[4][4];
        #pragma unroll
        for (int a = 0; a < 4; a++)
            #pragma unroll
            for (int q = 0; q < 4; q++) c1[a][q] = 0.f;
        for (int k0 = 0; k0 < 16; k0++) {
            int kb = k0 * 8;
            float a0 = tf32r(zs[(rowb + lg) * 132 + kb + lt]);
            float a1 = tf32r(zs[(rowb + lg + 8) * 132 + kb + lt]);
            float a2 = tf32r(zs[(rowb + lg) * 132 + kb + lt + 4]);
            float a3 = tf32r(zs[(rowb + lg + 8) * 132 + kb + lt + 4]);
            #pragma unroll
            for (int nt = 0; nt < 4; nt++) {
                int nb = wn * 32 + nt * 8;
                float bb0 = wb[(kb + lt) * 72 + nb + lg];
                float bb1 = wb[(kb + lt + 4) * 72 + nb + lg];
                mma_tf32(c1[nt], a0, a1, a2, a3, bb0, bb1);
            }
        }
        // bias + gelu -> hd (tf32-rounded)
        #pragma unroll
        for (int nt = 0; nt < 4; nt++) {
            #pragma unroll
            for (int q = 0; q < 4; q++) {
                int rr = rowb + lg + ((q >= 2) ? 8 : 0);
                int cc = wn * 32 + nt * 8 + lt * 2 + (q & 1);
                float x = c1[nt][q] + b1[hc * 64 + cc];
                float t = tanhf(0.7978845608028654f * (x + 0.044715f * x * x * x));
                hd[rr * 72 + cc] = tf32r(0.5f * x * (1.f + t));
            }
        }
        __syncthreads();   // all warps done with W1 in wb; hd written
        // stage W2 chunk [k 64][c 128] -> wb stride 136 (tf32-rounded)
        for (int i = tid; i < 8192; i += 256) {
            int k = i >> 7, c = i & 127;
            wb[k * 136 + c] = tf32r(w2[(hc * 64 + k) * 128 + c]);
        }
        __syncthreads();
        // GEMM2 partial: C2[64 x 128] += hd[64 x 64] @ W2chunk[64 x 128]; per warp m16 x n64
        for (int k0 = 0; k0 < 8; k0++) {
            int kb = k0 * 8;
            float a0 = hd[(rowb + lg) * 72 + kb + lt];
            float a1 = hd[(rowb + lg + 8) * 72 + kb + lt];
            float a2 = hd[(rowb + lg) * 72 + kb + lt + 4];
            float a3 = hd[(rowb + lg + 8) * 72 + kb + lt + 4];
            #pragma unroll
            for (int nt = 0; nt < 8; nt++) {
                int nb = wn * 64 + nt * 8;
                float bb0 = wb[(kb + lt) * 136 + nb + lg];
                float bb1 = wb[(kb + lt + 4) * 136 + nb + lg];
                mma_tf32(c2[nt], a0, a1, a2, a3, bb0, bb1);
            }
        }
    }
    __syncthreads();
    // stage C2 -> ob[c][w] (reuse wb), stride 66
    float* ob = wb;
    #pragma unroll
    for (int nt = 0; nt < 8; nt++) {
        #pragma unroll
        for (int q = 0; q < 4; q++) {
            int rr = rowb + lg + ((q >= 2) ? 8 : 0);
            int cc = wn * 64 + nt * 8 + lt * 2 + (q & 1);
            ob[cc * 66 + rr] = c2[nt][q];
        }
    }
    __syncthreads();
    // epilogue: out = xsp + z + (o + b2), coalesced over w
    for (int i = tid; i < 8192; i += 256) {
        int c = i >> 6, w = i & 63;
        float o = ob[c * 66 + w] + b2[c];
        float zv = zs[w * 132 + c];
        int d = c & 63;
        int gidx = ((n * 64 + d) * 64 + h) * 64 + w;
        if (c < 64) out[OUT_RE + gidx] = g_xsp_re[gidx] + zv + o;
        else        out[OUT_IM + gidx] = g_xsp_im[gidx] + zv + o;
    }
}

// ---------------- launch ----------------
extern "C" void kernel_launch(void* const* d_in, const int* in_sizes, int n_in,
                              void* d_out, int out_size) {
    const float* x_re      = (const float*)d_in[0];
    const float* x_im      = (const float*)d_in[1];
    const float* h_prev_re = (const float*)d_in[2];
    const float* h_prev_im = (const float*)d_in[3];
    const float* flux_p_re = (const float*)d_in[4];
    const float* flux_p_im = (const float*)d_in[5];
    const float* dt        = (const float*)d_in[6];
    const float* ln_gamma  = (const float*)d_in[7];
    const float* ln_beta   = (const float*)d_in[8];
    const float* conv_w    = (const float*)d_in[9];
    const float* conv_b    = (const float*)d_in[10];
    const float* metric    = (const float*)d_in[11];
    const float* E_re      = (const float*)d_in[12];
    const float* E_im      = (const float*)d_in[13];
    const float* Edec_re   = (const float*)d_in[14];
    const float* Edec_im   = (const float*)d_in[15];
    const float* lam_h_re  = (const float*)d_in[16];
    const float* lam_h_im  = (const float*)d_in[17];
    const float* lam_f_re  = (const float*)d_in[18];
    const float* lam_f_im  = (const float*)d_in[19];
    const float* W_src_re  = (const float*)d_in[20];
    const float* W_src_im  = (const float*)d_in[21];
    const float* W_gate    = (const float*)d_in[22];
    const float* b_gate    = (const float*)d_in[23];
    const float* ffn_w1    = (const float*)d_in[24];
    const float* ffn_b1    = (const float*)d_in[25];
    const float* ffn_w2    = (const float*)d_in[26];
    const float* ffn_b2    = (const float*)d_in[27];
    float* out = (float*)d_out;

    const int smem_eig = (4096 * 2 + 64 * 65 * 2 + 64 * 129) * 4;          // 99072
    const int smem_ffn = (64 * 132 + 9216 + 64 * 72) * 4;                  // 89088
    cudaFuncSetAttribute(k_eig, cudaFuncAttributeMaxDynamicSharedMemorySize, smem_eig);
    cudaFuncSetAttribute(k_dec, cudaFuncAttributeMaxDynamicSharedMemorySize, smem_eig);
    cudaFuncSetAttribute(k_ffn, cudaFuncAttributeMaxDynamicSharedMemorySize, smem_ffn);

    k_ln  <<<NB * HH, 64>>>(x_re, x_im, ln_gamma, ln_beta);
    k_conv<<<NB * HH, 256>>>(x_re, x_im, conv_w, conv_b, metric);
    k_eig <<<NB * HH, 256, smem_eig>>>(E_re, E_im);
    k_flux1<<<1, 256>>>(dt, lam_f_re, lam_f_im, lam_h_re, lam_h_im,
                        flux_p_re, flux_p_im, out);
    k_flux2<<<32, 64>>>(W_src_re, W_src_im, W_gate, b_gate);
    k_scan<<<4096, 256>>>(h_prev_re, h_prev_im, out);
    k_dec <<<NB * HH, 256, smem_eig>>>(Edec_re, Edec_im);
    k_ffn <<<NB * HH, 256, smem_ffn>>>(ffn_w1, ffn_b1, ffn_w2, ffn_b2, out);
}

// round 12
// speedup vs baseline: 2.7341x; 1.4406x over previous
#include <cuda_runtime.h>
#include <cuda_bf16.h>
#include <math.h>

// ---------------- problem constants ----------------
#define NB 32          // B*T
#define D64 64
#define HH 64
#define WW 64
#define HW 4096
#define C2 128
#define BB 4
#define TT 8

// output regions (floats)
#define OUT_RE   0
#define OUT_IM   8388608
#define HOUT_RE  16777216
#define HOUT_IM  (16777216 + 1048576)
#define FLUX_RE  (16777216 + 2097152)
#define FLUX_IM  (FLUX_RE + 256)

// ---------------- scratch (device globals; no allocation) ----------------
__device__ float g_xn[NB * C2 * HW];          // layernormed, (n,c,h,w)
__device__ float g_wt2[9 * 128 * 128];        // conv weights transposed: [tap][ci][co]
__device__ float g_xsp_re[NB * D64 * HW];     // (n,d,h,w)
__device__ float g_xsp_im[NB * D64 * HW];
__device__ float g_xeig_re[NB * HW * D64];    // (n,h,w,e)
__device__ float g_xeig_im[NB * HW * D64];
__device__ float g_y_re[NB * HW * D64];       // (n,h,w,e)
__device__ float g_y_im[NB * HW * D64];
__device__ float g_z[NB * HW * C2];           // rows: [re(64), im(64)]
__device__ float g_sum_re[BB * TT * D64];     // 2048 (for x_mean)
__device__ float g_sum_im[BB * TT * D64];
__device__ float g_ff_re[BB * TT * D64];      // flux forcing
__device__ float g_ff_im[BB * TT * D64];
__device__ float g_gate[BB * TT * D64];
__device__ float g_src_re[BB * TT * D64];
__device__ float g_src_im[BB * TT * D64];
__device__ float g_ah_re[D64], g_ah_im[D64];
__device__ float g_ch_re[D64], g_ch_im[D64];

// ---------------- tf32 helpers ----------------
__device__ __forceinline__ float tf32r(float x) {
    float y; asm("cvt.rna.tf32.f32 %0, %1;" : "=f"(y) : "f"(x)); return y;
}
__device__ __forceinline__ void mma_tf32(float* c, float a0, float a1, float a2, float a3,
                                         float b0, float b1) {
    asm volatile("mma.sync.aligned.m16n8k8.row.col.f32.tf32.tf32.f32 "
        "{%0,%1,%2,%3}, {%4,%5,%6,%7}, {%8,%9}, {%0,%1,%2,%3};"
        : "+f"(c[0]), "+f"(c[1]), "+f"(c[2]), "+f"(c[3])
        : "r"(__float_as_uint(a0)), "r"(__float_as_uint(a1)),
          "r"(__float_as_uint(a2)), "r"(__float_as_uint(a3)),
          "r"(__float_as_uint(b0)), "r"(__float_as_uint(b1)));
}

// ---------------- kernel 0: transpose conv weights -> [tap][ci][co] ----------------
__global__ void k_wtr(const float* __restrict__ cw) {
    int idx = blockIdx.x * 256 + threadIdx.x;
    if (idx >= 9 * 128 * 128) return;
    int co = idx & 127;
    int rest = idx >> 7;
    int ci = rest & 127;
    int tap = rest >> 7;
    g_wt2[idx] = cw[(co * 128 + ci) * 9 + tap];
}

// ---------------- kernel 1: layernorm over 128 channels ----------------
__global__ void k_ln(const float* __restrict__ xre, const float* __restrict__ xim,
                     const float* __restrict__ gamma, const float* __restrict__ beta) {
    int n = blockIdx.x >> 6, h = blockIdx.x & 63;
    int w = threadIdx.x;  // 64 threads
    if (blockIdx.x == 0) {
        for (int i = w; i < BB * TT * D64; i += 64) { g_sum_re[i] = 0.f; g_sum_im[i] = 0.f; }
    }
    int base0 = n * 262144 + h * 64 + w;   // (n, d=0, h, w); d-stride 4096
    float s = 0.f, s2 = 0.f;
    #pragma unroll 4
    for (int c = 0; c < 64; c++) { float v = xre[base0 + c * 4096]; s += v; s2 += v * v; }
    #pragma unroll 4
    for (int c = 0; c < 64; c++) { float v = xim[base0 + c * 4096]; s += v; s2 += v * v; }
    float mu  = s * (1.f / 128.f);
    float var = s2 * (1.f / 128.f) - mu * mu;
    float inv = rsqrtf(var + 1e-5f);
    int ob = n * (C2 * HW) + h * 64 + w;
    #pragma unroll 4
    for (int c = 0; c < 128; c++) {
        float v = (c < 64) ? xre[base0 + c * 4096] : xim[base0 + (c - 64) * 4096];
        g_xn[ob + c * 4096] = (v - mu) * inv * gamma[c] + beta[c];
    }
}

// ---------------- kernel 2: conv 3x3 via tf32 mma (9 shifted GEMMs) ----------------
// One block per (n,h). M=64 (w), N=128 (co), K=1152 (ci x 9 taps).
// ci chunked by 32; per tap a K=32 GEMM with shifted A reads.
// Warp grid 4x2: per warp m16 x n64, c2[8][4] accumulators (same as k_ffn GEMM2).
__global__ void __launch_bounds__(256) k_conv(
        const float* __restrict__ xre, const float* __restrict__ xim,
        const float* __restrict__ cb, const float* __restrict__ metric) {
    extern __shared__ float sm[];
    float* s_in = sm;             // 32 ci x 3 rows x 68 = 6528 floats
    float* s_w  = sm + 6528;      // 32 k x 132 = 4224 floats
    // epilogue ob overlays sm: 128 x 66 = 8448 floats (< 10752 total)
    int n = blockIdx.x >> 6, h = blockIdx.x & 63;
    int tid = threadIdx.x;
    int lane = tid & 31, warp = tid >> 5;
    int wm = warp >> 1, wn = warp & 1;
    int rowb = wm * 16;
    int lg = lane >> 2;           // 0..7
    int lt = lane & 3;            // 0..3

    float c2[8][4];
    #pragma unroll
    for (int a = 0; a < 8; a++)
        #pragma unroll
        for (int q = 0; q < 4; q++) c2[a][q] = 0.f;

    for (int cc0 = 0; cc0 < 128; cc0 += 32) {
        __syncthreads();   // previous chunk's GEMM reads of s_in done
        // stage input chunk: [ci 32][r 3][wp 68], wp = w+1 (w in -1..64), wp 66,67 = pad
        for (int i = tid; i < 6528; i += 256) {
            int ci = i / 204;
            int rem = i - ci * 204;
            int r = rem / 68, wp = rem - r * 68;
            int hh = h + r - 1, ww = wp - 1;
            float v = 0.f;
            if (hh >= 0 && hh < 64 && ww >= 0 && ww < 64 && wp < 66)
                v = g_xn[((n * 128 + cc0 + ci) * 64 + hh) * 64 + ww];
            s_in[i] = v;
        }
        for (int tap = 0; tap < 9; tap++) {
            __syncthreads();   // s_in visible (tap 0) / previous tap's s_w reads done
            // stage weights [k 32][co 128] stride 132, tf32-rounded
            for (int i = tid; i < 4096; i += 256) {
                int k = i >> 7, co = i & 127;
                s_w[k * 132 + co] = tf32r(g_wt2[(tap * 128 + cc0 + k) * 128 + co]);
            }
            __syncthreads();
            int dh = tap / 3, dw = tap - dh * 3;
            int abase = dh * 68 + rowb + dw;   // w index offset: rowb+lg + dw (wp = w+1 -> +dw-1+1)
            #pragma unroll
            for (int k0 = 0; k0 < 4; k0++) {
                int kb = k0 * 8;
                float a0 = tf32r(s_in[(kb + lt) * 204 + abase + lg]);
                float a1 = tf32r(s_in[(kb + lt) * 204 + abase + lg + 8]);
                float a2 = tf32r(s_in[(kb + lt + 4) * 204 + abase + lg]);
                float a3 = tf32r(s_in[(kb + lt + 4) * 204 + abase + lg + 8]);
                #pragma unroll
                for (int nt = 0; nt < 8; nt++) {
                    int nb = wn * 64 + nt * 8;
                    float bb0 = s_w[(kb + lt) * 132 + nb + lg];
                    float bb1 = s_w[(kb + lt + 4) * 132 + nb + lg];
                    mma_tf32(c2[nt], a0, a1, a2, a3, bb0, bb1);
                }
            }
        }
    }
    __syncthreads();
    // stage C2 -> ob[co][w] stride 66 (overlays sm)
    float* ob = sm;
    #pragma unroll
    for (int nt = 0; nt < 8; nt++) {
        #pragma unroll
        for (int q = 0; q < 4; q++) {
            int rr = rowb + lg + ((q >= 2) ? 8 : 0);
            int cc = wn * 64 + nt * 8 + lt * 2 + (q & 1);
            ob[cc * 66 + rr] = c2[nt][q];
        }
    }
    __syncthreads();
    // epilogue: xsp = x + (conv + bias) * metric, coalesced over w
    for (int i = tid; i < 8192; i += 256) {
        int c = i >> 6, w = i & 63;
        float val = (ob[c * 66 + w] + cb[c]) * metric[h * 64 + w];
        if (c < 64) {
            int idx = ((n * 64 + c) * 64 + h) * 64 + w;
            g_xsp_re[idx] = xre[idx] + val;
        } else {
            int idx = ((n * 64 + (c - 64)) * 64 + h) * 64 + w;
            g_xsp_im[idx] = xim[idx] + val;
        }
    }
}

// ---------------- kernel 3: x_eig = xsp @ E (complex) + H,W-mean partial sums (scalar R1) ----------------
__global__ void __launch_bounds__(256) k_eig(const float* __restrict__ Er, const float* __restrict__ Ei) {
    extern __shared__ float sm[];
    float* sEr = sm;                 // 4096
    float* sEi = sEr + 4096;         // 4096
    float* sXr = sEi + 4096;         // 64*65  [d][w] padded
    float* sXi = sXr + 64 * 65;
    float* sOut = sXi + 64 * 65;     // 64*129 [w][e] padded
    int n = blockIdx.x >> 6, h = blockIdx.x & 63;
    int tid = threadIdx.x;
    int w = tid & 63;
    int eg = tid >> 6;               // 4 groups * 16 e
    for (int i = tid; i < 4096; i += 256) {
        sEr[i] = Er[i]; sEi[i] = Ei[i];
        int d = i >> 6, ww = i & 63;
        int gi = ((n * 64 + d) * 64 + h) * 64 + ww;
        sXr[d * 65 + ww] = g_xsp_re[gi];
        sXi[d * 65 + ww] = g_xsp_im[gi];
    }
    __syncthreads();
    float ar[16], ai[16];
    #pragma unroll
    for (int k = 0; k < 16; k++) { ar[k] = 0.f; ai[k] = 0.f; }
    for (int d = 0; d < 64; d++) {
        float xr = sXr[d * 65 + w], xi = sXi[d * 65 + w];
        #pragma unroll
        for (int k = 0; k < 16; k++) {
            int e = eg * 16 + k;
            float er = sEr[d * 64 + e], ei = sEi[d * 64 + e];
            ar[k] += xr * er - xi * ei;
            ai[k] += xr * ei + xi * er;
        }
    }
    #pragma unroll
    for (int k = 0; k < 16; k++) {
        float sr = ar[k], si = ai[k];
        #pragma unroll
        for (int off = 16; off > 0; off >>= 1) {
            sr += __shfl_xor_sync(0xffffffff, sr, off);
            si += __shfl_xor_sync(0xffffffff, si, off);
        }
        if ((tid & 31) == 0) {
            atomicAdd(&g_sum_re[n * 64 + eg * 16 + k], sr);
            atomicAdd(&g_sum_im[n * 64 + eg * 16 + k], si);
        }
    }
    int base = (n * 64 + h) * 4096;
    #pragma unroll
    for (int k = 0; k < 16; k++) sOut[w * 129 + eg * 16 + k] = ar[k];
    __syncthreads();
    for (int i = tid; i < 4096; i += 256) g_xeig_re[base + i] = sOut[(i >> 6) * 129 + (i & 63)];
    __syncthreads();
    #pragma unroll
    for (int k = 0; k < 16; k++) sOut[w * 129 + eg * 16 + k] = ai[k];
    __syncthreads();
    for (int i = tid; i < 4096; i += 256) g_xeig_im[base + i] = sOut[(i >> 6) * 129 + (i & 63)];
}

// ---------------- kernel 4a: flux recurrence + a_h/c_h ----------------
__global__ void k_flux1(const float* __restrict__ dtp,
                        const float* __restrict__ lfre, const float* __restrict__ lfim,
                        const float* __restrict__ lhre, const float* __restrict__ lhim,
                        const float* __restrict__ fpre, const float* __restrict__ fpim,
                        float* __restrict__ out) {
    int tid = threadIdx.x;           // 256
    int b = tid >> 6, d = tid & 63;
    float dtv = dtp[0];
    float lfr = -fabsf(lfre[d]), lfi = lfim[d];
    float efac = expf(lfr * dtv);
    float afr = efac * cosf(lfi * dtv), afi = efac * sinf(lfi * dtv);
    float den = lfr * lfr + lfi * lfi;
    float nr = afr - 1.f, ni = afi;
    float cfr = (nr * lfr + ni * lfi) / den;
    float cfi = (ni * lfr - nr * lfi) / den;
    float fr = fpre[b * 64 + d], fi = fpim[b * 64 + d];
    for (int t = 0; t < TT; t++) {
        g_ff_re[(b * TT + t) * 64 + d] = fr;
        g_ff_im[(b * TT + t) * 64 + d] = fi;
        float xmr = g_sum_re[(b * TT + t) * 64 + d] * (1.f / 4096.f);
        float xmi = g_sum_im[(b * TT + t) * 64 + d] * (1.f / 4096.f);
        float ur = xmr * cfr - xmi * cfi;
        float ui = xmr * cfi + xmi * cfr;
        float nfr = afr * fr - afi * fi + ur;
        float nfi = afr * fi + afi * fr + ui;
        fr = nfr; fi = nfi;
    }
    out[FLUX_RE + b * 64 + d] = fr;
    out[FLUX_IM + b * 64 + d] = fi;

    if (tid < 64) {
        float lr = -fabsf(lhre[tid]), li = lhim[tid];
        float e2 = expf(lr * dtv);
        float ahr = e2 * cosf(li * dtv), ahi = e2 * sinf(li * dtv);
        float dd = lr * lr + li * li;
        float mr = ahr - 1.f, mi = ahi;
        g_ah_re[tid] = ahr; g_ah_im[tid] = ahi;
        g_ch_re[tid] = (mr * lr + mi * li) / dd;
        g_ch_im[tid] = (mi * lr - mr * li) / dd;
    }
}

// ---------------- kernel 4b: source & gate ----------------
__global__ void k_flux2(const float* __restrict__ Wsr, const float* __restrict__ Wsi,
                        const float* __restrict__ Wg,  const float* __restrict__ bg) {
    int blk = blockIdx.x;            // 32 = B*T
    int e = threadIdx.x;             // 64
    __shared__ float sfr[64], sfi[64];
    sfr[e] = g_ff_re[blk * 64 + e];
    sfi[e] = g_ff_im[blk * 64 + e];
    __syncthreads();
    float sr = 0.f, si = 0.f, ga = bg[e];
    #pragma unroll 4
    for (int dd = 0; dd < 64; dd++) {
        float ffr = sfr[dd], ffi = sfi[dd];
        float wr = Wsr[dd * 64 + e], wi = Wsi[dd * 64 + e];
        sr += ffr * wr - ffi * wi;
        si += ffr * wi + ffi * wr;
        ga += ffr * Wg[dd * 64 + e];
    }
    int q = blk * 64 + e;
    g_src_re[q] = sr;
    g_src_im[q] = si;
    g_gate[q] = 1.f / (1.f + expf(-ga));
}

// ---------------- kernel 5: T-scan for y + h_out ----------------
__global__ void k_scan(const float* __restrict__ hpr, const float* __restrict__ hpi,
                       float* __restrict__ out) {
    int gid = blockIdx.x * 256 + threadIdx.x;    // 1048576 threads
    int e = gid & 63;
    int pos = gid >> 6;                          // b*4096 + hw
    int b = pos >> 12, hw = pos & 4095;
    float ahr = g_ah_re[e], ahi = g_ah_im[e];
    float chr = g_ch_re[e], chi = g_ch_im[e];
    float yr = hpr[gid], yi = hpi[gid];
    #pragma unroll
    for (int t = 0; t < TT; t++) {
        int idx = ((b * TT + t) * 4096 + hw) * 64 + e;
        float xr = g_xeig_re[idx], xi = g_xeig_im[idx];
        int q = (b * TT + t) * 64 + e;
        float gg = g_gate[q];
        float sr = g_src_re[q], si = g_src_im[q];
        float fr = xr * gg + sr * (1.f - gg);
        float fi = xi * gg + si * (1.f - gg);
        float ur = fr * chr - fi * chi;
        float ui = fr * chi + fi * chr;
        float nyr = ahr * yr - ahi * yi + ur;
        float nyi = ahr * yi + ahi * yr + ui;
        yr = nyr; yi = nyi;
        g_y_re[idx] = yr; g_y_im[idx] = yi;
    }
    out[HOUT_RE + gid] = yr;
    out[HOUT_IM + gid] = yi;
}

// ---------------- kernel 6: y_dec = y @ Edec (complex) -> z rows (scalar R1) ----------------
__global__ void __launch_bounds__(256) k_dec(const float* __restrict__ Er, const float* __restrict__ Ei) {
    extern __shared__ float sm[];
    float* sEr = sm;
    float* sEi = sEr + 4096;
    float* sYr = sEi + 4096;          // [w][d] padded 65
    float* sYi = sYr + 64 * 65;
    float* sOut = sYi + 64 * 65;      // [w][c] padded 129
    int n = blockIdx.x >> 6, h = blockIdx.x & 63;
    int tid = threadIdx.x;
    int w = tid & 63;
    int eg = tid >> 6;
    int base = (n * 64 + h) * 4096;
    for (int i = tid; i < 4096; i += 256) {
        sEr[i] = Er[i]; sEi[i] = Ei[i];
        sYr[(i >> 6) * 65 + (i & 63)] = g_y_re[base + i];
        sYi[(i >> 6) * 65 + (i & 63)] = g_y_im[base + i];
    }
    __syncthreads();
    float ar[16], ai[16];
    #pragma unroll
    for (int k = 0; k < 16; k++) { ar[k] = 0.f; ai[k] = 0.f; }
    for (int d = 0; d < 64; d++) {
        float xr = sYr[w * 65 + d], xi = sYi[w * 65 + d];
        #pragma unroll
        for (int k = 0; k < 16; k++) {
            int e = eg * 16 + k;
            float er = sEr[d * 64 + e], ei = sEi[d * 64 + e];
            ar[k] += xr * er - xi * ei;
            ai[k] += xr * ei + xi * er;
        }
    }
    #pragma unroll
    for (int k = 0; k < 16; k++) {
        sOut[w * 129 + eg * 16 + k] = ar[k];
        sOut[w * 129 + 64 + eg * 16 + k] = ai[k];
    }
    __syncthreads();
    int zb = (n * 64 + h) * 8192;
    for (int i = tid; i < 8192; i += 256)
        g_z[zb + i] = sOut[(i >> 7) * 129 + (i & 127)];
}

// ---------------- kernel 7: fused FFN via tf32 mma.sync + final residual ----------------
__global__ void __launch_bounds__(256) k_ffn(const float* __restrict__ w1, const float* __restrict__ b1,
                                             const float* __restrict__ w2, const float* __restrict__ b2,
                                             float* __restrict__ out) {
    extern __shared__ float sm[];
    float* zs = sm;                   // 64 x 132  (rows x cols, fp32 exact)
    float* wb = zs + 64 * 132;        // 9216 floats: W1 chunk [128][72] / W2 chunk [64][136] / ob [128][66]
    float* hd = wb + 9216;            // 64 x 72   hidden chunk (tf32-rounded)
    int blk = blockIdx.x;             // 2048
    int n = blk >> 6, h = blk & 63;
    int tid = threadIdx.x;
    int lane = tid & 31, warp = tid >> 5;
    int wm = warp >> 1, wn = warp & 1;
    int rowb = wm * 16;
    int lg = lane >> 2;               // groupID 0..7
    int lt = lane & 3;                // threadInGroup 0..3
    int rowbase = (n * 64 + h) * 64;  // global z row base

    for (int i = tid; i < 8192; i += 256)
        zs[(i >> 7) * 132 + (i & 127)] = g_z[(rowbase + (i >> 7)) * 128 + (i & 127)];

    float c2[8][4];
    #pragma unroll
    for (int a = 0; a < 8; a++)
        #pragma unroll
        for (int q = 0; q < 4; q++) c2[a][q] = 0.f;

    for (int hc = 0; hc < 8; hc++) {
        __syncthreads();
        for (int i = tid; i < 8192; i += 256) {
            int k = i >> 6, j = i & 63;
            wb[k * 72 + j] = tf32r(w1[k * 512 + hc * 64 + j]);
        }
        __syncthreads();
        float c1[4][4];
        #pragma unroll
        for (int a = 0; a < 4; a++)
            #pragma unroll
            for (int q = 0; q < 4; q++) c1[a][q] = 0.f;
        for (int k0 = 0; k0 < 16; k0++) {
            int kb = k0 * 8;
            float a0 = tf32r(zs[(rowb + lg) * 132 + kb + lt]);
            float a1 = tf32r(zs[(rowb + lg + 8) * 132 + kb + lt]);
            float a2 = tf32r(zs[(rowb + lg) * 132 + kb + lt + 4]);
            float a3 = tf32r(zs[(rowb + lg + 8) * 132 + kb + lt + 4]);
            #pragma unroll
            for (int nt = 0; nt < 4; nt++) {
                int nb = wn * 32 + nt * 8;
                float bb0 = wb[(kb + lt) * 72 + nb + lg];
                float bb1 = wb[(kb + lt + 4) * 72 + nb + lg];
                mma_tf32(c1[nt], a0, a1, a2, a3, bb0, bb1);
            }
        }
        #pragma unroll
        for (int nt = 0; nt < 4; nt++) {
            #pragma unroll
            for (int q = 0; q < 4; q++) {
                int rr = rowb + lg + ((q >= 2) ? 8 : 0);
                int cc = wn * 32 + nt * 8 + lt * 2 + (q & 1);
                float x = c1[nt][q] + b1[hc * 64 + cc];
                float t = tanhf(0.7978845608028654f * (x + 0.044715f * x * x * x));
                hd[rr * 72 + cc] = tf32r(0.5f * x * (1.f + t));
            }
        }
        __syncthreads();
        for (int i = tid; i < 8192; i += 256) {
            int k = i >> 7, c = i & 127;
            wb[k * 136 + c] = tf32r(w2[(hc * 64 + k) * 128 + c]);
        }
        __syncthreads();
        for (int k0 = 0; k0 < 8; k0++) {
            int kb = k0 * 8;
            float a0 = hd[(rowb + lg) * 72 + kb + lt];
            float a1 = hd[(rowb + lg + 8) * 72 + kb + lt];
            float a2 = hd[(rowb + lg) * 72 + kb + lt + 4];
            float a3 = hd[(rowb + lg + 8) * 72 + kb + lt + 4];
            #pragma unroll
            for (int nt = 0; nt < 8; nt++) {
                int nb = wn * 64 + nt * 8;
                float bb0 = wb[(kb + lt) * 136 + nb + lg];
                float bb1 = wb[(kb + lt + 4) * 136 + nb + lg];
                mma_tf32(c2[nt], a0, a1, a2, a3, bb0, bb1);
            }
        }
    }
    __syncthreads();
    float* ob = wb;
    #pragma unroll
    for (int nt = 0; nt < 8; nt++) {
        #pragma unroll
        for (int q = 0; q < 4; q++) {
            int rr = rowb + lg + ((q >= 2) ? 8 : 0);
            int cc = wn * 64 + nt * 8 + lt * 2 + (q & 1);
            ob[cc * 66 + rr] = c2[nt][q];
        }
    }
    __syncthreads();
    for (int i = tid; i < 8192; i += 256) {
        int c = i >> 6, w = i & 63;
        float o = ob[c * 66 + w] + b2[c];
        float zv = zs[w * 132 + c];
        int d = c & 63;
        int gidx = ((n * 64 + d) * 64 + h) * 64 + w;
        if (c < 64) out[OUT_RE + gidx] = g_xsp_re[gidx] + zv + o;
        else        out[OUT_IM + gidx] = g_xsp_im[gidx] + zv + o;
    }
}

// ---------------- launch ----------------
extern "C" void kernel_launch(void* const* d_in, const int* in_sizes, int n_in,
                              void* d_out, int out_size) {
    const float* x_re      = (const float*)d_in[0];
    const float* x_im      = (const float*)d_in[1];
    const float* h_prev_re = (const float*)d_in[2];
    const float* h_prev_im = (const float*)d_in[3];
    const float* flux_p_re = (const float*)d_in[4];
    const float* flux_p_im = (const float*)d_in[5];
    const float* dt        = (const float*)d_in[6];
    const float* ln_gamma  = (const float*)d_in[7];
    const float* ln_beta   = (const float*)d_in[8];
    const float* conv_w    = (const float*)d_in[9];
    const float* conv_b    = (const float*)d_in[10];
    const float* metric    = (const float*)d_in[11];
    const float* E_re      = (const float*)d_in[12];
    const float* E_im      = (const float*)d_in[13];
    const float* Edec_re   = (const float*)d_in[14];
    const float* Edec_im   = (const float*)d_in[15];
    const float* lam_h_re  = (const float*)d_in[16];
    const float* lam_h_im  = (const float*)d_in[17];
    const float* lam_f_re  = (const float*)d_in[18];
    const float* lam_f_im  = (const float*)d_in[19];
    const float* W_src_re  = (const float*)d_in[20];
    const float* W_src_im  = (const float*)d_in[21];
    const float* W_gate    = (const float*)d_in[22];
    const float* b_gate    = (const float*)d_in[23];
    const float* ffn_w1    = (const float*)d_in[24];
    const float* ffn_b1    = (const float*)d_in[25];
    const float* ffn_w2    = (const float*)d_in[26];
    const float* ffn_b2    = (const float*)d_in[27];
    float* out = (float*)d_out;

    const int smem_eig  = (4096 * 2 + 64 * 65 * 2 + 64 * 129) * 4;         // 99072
    const int smem_ffn  = (64 * 132 + 9216 + 64 * 72) * 4;                 // 89088
    const int smem_conv = (6528 + 4224) * 4;                               // 43008
    cudaFuncSetAttribute(k_eig, cudaFuncAttributeMaxDynamicSharedMemorySize, smem_eig);
    cudaFuncSetAttribute(k_dec, cudaFuncAttributeMaxDynamicSharedMemorySize, smem_eig);
    cudaFuncSetAttribute(k_ffn, cudaFuncAttributeMaxDynamicSharedMemorySize, smem_ffn);
    cudaFuncSetAttribute(k_conv, cudaFuncAttributeMaxDynamicSharedMemorySize, smem_conv);

    k_wtr <<<(9 * 128 * 128 + 255) / 256, 256>>>(conv_w);
    k_ln  <<<NB * HH, 64>>>(x_re, x_im, ln_gamma, ln_beta);
    k_conv<<<NB * HH, 256, smem_conv>>>(x_re, x_im, conv_b, metric);
    k_eig <<<NB * HH, 256, smem_eig>>>(E_re, E_im);
    k_flux1<<<1, 256>>>(dt, lam_f_re, lam_f_im, lam_h_re, lam_h_im,
                        flux_p_re, flux_p_im, out);
    k_flux2<<<32, 64>>>(W_src_re, W_src_im, W_gate, b_gate);
    k_scan<<<4096, 256>>>(h_prev_re, h_prev_im, out);
    k_dec <<<NB * HH, 256, smem_eig>>>(Edec_re, Edec_im);
    k_ffn <<<NB * HH, 256, smem_ffn>>>(ffn_w1, ffn_b1, ffn_w2, ffn_b2, out);
}

// round 14
// speedup vs baseline: 2.9216x; 1.0686x over previous
#include <cuda_runtime.h>
#include <cuda_bf16.h>
#include <math.h>

// ---------------- problem constants ----------------
#define NB 32          // B*T
#define D64 64
#define HH 64
#define WW 64
#define HW 4096
#define C2 128
#define BB 4
#define TT 8

// output regions (floats)
#define OUT_RE   0
#define OUT_IM   8388608
#define HOUT_RE  16777216
#define HOUT_IM  (16777216 + 1048576)
#define FLUX_RE  (16777216 + 2097152)
#define FLUX_IM  (FLUX_RE + 256)

// ---------------- scratch (device globals; no allocation) ----------------
__device__ float g_xn[NB * C2 * HW];          // layernormed, (n,c,h,w)
__device__ float g_wt2[9 * 128 * 128];        // conv weights transposed: [tap][ci][co]
__device__ float g_xsp_re[NB * D64 * HW];     // (n,d,h,w)
__device__ float g_xsp_im[NB * D64 * HW];
__device__ float g_xeig_re[NB * HW * D64];    // (n,h,w,e)
__device__ float g_xeig_im[NB * HW * D64];
__device__ float g_y_re[NB * HW * D64];       // (n,h,w,e)
__device__ float g_y_im[NB * HW * D64];
__device__ float g_z[NB * HW * C2];           // rows: [re(64), im(64)]
__device__ float g_sum_re[BB * TT * D64];     // 2048 (for x_mean)
__device__ float g_sum_im[BB * TT * D64];
__device__ float g_ff_re[BB * TT * D64];      // flux forcing
__device__ float g_ff_im[BB * TT * D64];
__device__ float g_gate[BB * TT * D64];
__device__ float g_src_re[BB * TT * D64];
__device__ float g_src_im[BB * TT * D64];
__device__ float g_ah_re[D64], g_ah_im[D64];
__device__ float g_ch_re[D64], g_ch_im[D64];

// ---------------- tf32 helpers ----------------
__device__ __forceinline__ float tf32r(float x) {
    float y; asm("cvt.rna.tf32.f32 %0, %1;" : "=f"(y) : "f"(x)); return y;
}
__device__ __forceinline__ void mma_tf32(float* c, float a0, float a1, float a2, float a3,
                                         float b0, float b1) {
    asm volatile("mma.sync.aligned.m16n8k8.row.col.f32.tf32.tf32.f32 "
        "{%0,%1,%2,%3}, {%4,%5,%6,%7}, {%8,%9}, {%0,%1,%2,%3};"
        : "+f"(c[0]), "+f"(c[1]), "+f"(c[2]), "+f"(c[3])
        : "r"(__float_as_uint(a0)), "r"(__float_as_uint(a1)),
          "r"(__float_as_uint(a2)), "r"(__float_as_uint(a3)),
          "r"(__float_as_uint(b0)), "r"(__float_as_uint(b1)));
}

// ---------------- kernel 0: transpose conv weights -> [tap][ci][co] ----------------
__global__ void k_wtr(const float* __restrict__ cw) {
    int idx = blockIdx.x * 256 + threadIdx.x;
    if (idx >= 9 * 128 * 128) return;
    int co = idx & 127;
    int rest = idx >> 7;
    int ci = rest & 127;
    int tap = rest >> 7;
    g_wt2[idx] = cw[(co * 128 + ci) * 9 + tap];
}

// ---------------- kernel 1: layernorm over 128 channels ----------------
__global__ void k_ln(const float* __restrict__ xre, const float* __restrict__ xim,
                     const float* __restrict__ gamma, const float* __restrict__ beta) {
    int n = blockIdx.x >> 6, h = blockIdx.x & 63;
    int w = threadIdx.x;  // 64 threads
    if (blockIdx.x == 0) {
        for (int i = w; i < BB * TT * D64; i += 64) { g_sum_re[i] = 0.f; g_sum_im[i] = 0.f; }
    }
    int base0 = n * 262144 + h * 64 + w;   // (n, d=0, h, w); d-stride 4096
    float s = 0.f, s2 = 0.f;
    #pragma unroll 4
    for (int c = 0; c < 64; c++) { float v = xre[base0 + c * 4096]; s += v; s2 += v * v; }
    #pragma unroll 4
    for (int c = 0; c < 64; c++) { float v = xim[base0 + c * 4096]; s += v; s2 += v * v; }
    float mu  = s * (1.f / 128.f);
    float var = s2 * (1.f / 128.f) - mu * mu;
    float inv = rsqrtf(var + 1e-5f);
    int ob = n * (C2 * HW) + h * 64 + w;
    #pragma unroll 4
    for (int c = 0; c < 128; c++) {
        float v = (c < 64) ? xre[base0 + c * 4096] : xim[base0 + (c - 64) * 4096];
        g_xn[ob + c * 4096] = (v - mu) * inv * gamma[c] + beta[c];
    }
}

// ---------------- kernel 2: conv 3x3 via tf32 mma (9 shifted GEMMs) ----------------
__global__ void __launch_bounds__(256) k_conv(
        const float* __restrict__ xre, const float* __restrict__ xim,
        const float* __restrict__ cb, const float* __restrict__ metric) {
    extern __shared__ float sm[];
    float* s_in = sm;             // 32 ci x 3 rows x 68 = 6528 floats
    float* s_w  = sm + 6528;      // 32 k x 132 = 4224 floats
    int n = blockIdx.x >> 6, h = blockIdx.x & 63;
    int tid = threadIdx.x;
    int lane = tid & 31, warp = tid >> 5;
    int wm = warp >> 1, wn = warp & 1;
    int rowb = wm * 16;
    int lg = lane >> 2;           // 0..7
    int lt = lane & 3;            // 0..3

    float c2[8][4];
    #pragma unroll
    for (int a = 0; a < 8; a++)
        #pragma unroll
        for (int q = 0; q < 4; q++) c2[a][q] = 0.f;

    for (int cc0 = 0; cc0 < 128; cc0 += 32) {
        __syncthreads();
        for (int i = tid; i < 6528; i += 256) {
            int ci = i / 204;
            int rem = i - ci * 204;
            int r = rem / 68, wp = rem - r * 68;
            int hh = h + r - 1, ww = wp - 1;
            float v = 0.f;
            if (hh >= 0 && hh < 64 && ww >= 0 && ww < 64 && wp < 66)
                v = g_xn[((n * 128 + cc0 + ci) * 64 + hh) * 64 + ww];
            s_in[i] = v;
        }
        for (int tap = 0; tap < 9; tap++) {
            __syncthreads();
            for (int i = tid; i < 4096; i += 256) {
                int k = i >> 7, co = i & 127;
                s_w[k * 132 + co] = tf32r(g_wt2[(tap * 128 + cc0 + k) * 128 + co]);
            }
            __syncthreads();
            int dh = tap / 3, dw = tap - dh * 3;
            int abase = dh * 68 + rowb + dw;
            #pragma unroll
            for (int k0 = 0; k0 < 4; k0++) {
                int kb = k0 * 8;
                float a0 = tf32r(s_in[(kb + lt) * 204 + abase + lg]);
                float a1 = tf32r(s_in[(kb + lt) * 204 + abase + lg + 8]);
                float a2 = tf32r(s_in[(kb + lt + 4) * 204 + abase + lg]);
                float a3 = tf32r(s_in[(kb + lt + 4) * 204 + abase + lg + 8]);
                #pragma unroll
                for (int nt = 0; nt < 8; nt++) {
                    int nb = wn * 64 + nt * 8;
                    float bb0 = s_w[(kb + lt) * 132 + nb + lg];
                    float bb1 = s_w[(kb + lt + 4) * 132 + nb + lg];
                    mma_tf32(c2[nt], a0, a1, a2, a3, bb0, bb1);
                }
            }
        }
    }
    __syncthreads();
    float* ob = sm;
    #pragma unroll
    for (int nt = 0; nt < 8; nt++) {
        #pragma unroll
        for (int q = 0; q < 4; q++) {
            int rr = rowb + lg + ((q >= 2) ? 8 : 0);
            int cc = wn * 64 + nt * 8 + lt * 2 + (q & 1);
            ob[cc * 66 + rr] = c2[nt][q];
        }
    }
    __syncthreads();
    for (int i = tid; i < 8192; i += 256) {
        int c = i >> 6, w = i & 63;
        float val = (ob[c * 66 + w] + cb[c]) * metric[h * 64 + w];
        if (c < 64) {
            int idx = ((n * 64 + c) * 64 + h) * 64 + w;
            g_xsp_re[idx] = xre[idx] + val;
        } else {
            int idx = ((n * 64 + (c - 64)) * 64 + h) * 64 + w;
            g_xsp_im[idx] = xim[idx] + val;
        }
    }
}

// ---------------- kernel 3: x_eig via tf32 mma (complex as real M=64,N=128,K=128) ----------------
// A = [Xr | Xi] stored k-major sA[k][w]; B = [[Er, Ei], [-Ei, Er]] -> C = [out_re | out_im].
__global__ void __launch_bounds__(256) k_eig(const float* __restrict__ Er, const float* __restrict__ Ei) {
    extern __shared__ float sm[];
    float* sA = sm;               // 128 k x 65  (w + pad)
    float* sB = sm + 128 * 65;    // 128 k x 132 (n + pad)
    int n = blockIdx.x >> 6, h = blockIdx.x & 63;
    int tid = threadIdx.x;
    int lane = tid & 31, warp = tid >> 5;
    int wm = warp >> 1, wn = warp & 1;
    int rowb = wm * 16;
    int lg = lane >> 2;
    int lt = lane & 3;

    // stage A: k<64 -> Xr[d=k], k>=64 -> Xi[d=k-64]; coalesced global reads (consecutive w)
    for (int i = tid; i < 4096; i += 256) {
        int d = i >> 6, ww = i & 63;
        int gi = ((n * 64 + d) * 64 + h) * 64 + ww;
        sA[d * 65 + ww]        = g_xsp_re[gi];
        sA[(64 + d) * 65 + ww] = g_xsp_im[gi];
    }
    // stage B (tf32-rounded): rows k<64 from Xr-side: [Er | Ei]; rows k>=64 from Xi-side: [-Ei | Er]
    for (int i = tid; i < 4096; i += 256) {
        int d = i >> 6, e = i & 63;
        float er = Er[d * 64 + e], ei = Ei[d * 64 + e];
        sB[d * 132 + e]              = tf32r(er);
        sB[d * 132 + 64 + e]         = tf32r(ei);
        sB[(64 + d) * 132 + e]       = tf32r(-ei);
        sB[(64 + d) * 132 + 64 + e]  = tf32r(er);
    }
    __syncthreads();

    float c2[8][4];
    #pragma unroll
    for (int a = 0; a < 8; a++)
        #pragma unroll
        for (int q = 0; q < 4; q++) c2[a][q] = 0.f;
    #pragma unroll
    for (int k0 = 0; k0 < 16; k0++) {
        int kb = k0 * 8;
        float a0 = tf32r(sA[(kb + lt) * 65 + rowb + lg]);
        float a1 = tf32r(sA[(kb + lt) * 65 + rowb + lg + 8]);
        float a2 = tf32r(sA[(kb + lt + 4) * 65 + rowb + lg]);
        float a3 = tf32r(sA[(kb + lt + 4) * 65 + rowb + lg + 8]);
        #pragma unroll
        for (int nt = 0; nt < 8; nt++) {
            int nb = wn * 64 + nt * 8;
            float bb0 = sB[(kb + lt) * 132 + nb + lg];
            float bb1 = sB[(kb + lt + 4) * 132 + nb + lg];
            mma_tf32(c2[nt], a0, a1, a2, a3, bb0, bb1);
        }
    }
    __syncthreads();
    // stage C -> ob[nc][w] stride 66 (overlays sB region: 128*66 <= 128*132)
    float* ob = sB;
    #pragma unroll
    for (int nt = 0; nt < 8; nt++) {
        #pragma unroll
        for (int q = 0; q < 4; q++) {
            int rr = rowb + lg + ((q >= 2) ? 8 : 0);
            int cc = wn * 64 + nt * 8 + lt * 2 + (q & 1);
            ob[cc * 66 + rr] = c2[nt][q];
        }
    }
    __syncthreads();
    // H,W-mean partial: one column per thread (128 cols), sum 64 w's, one atomic
    if (tid < 128) {
        float s = 0.f;
        #pragma unroll 8
        for (int w = 0; w < 64; w++) s += ob[tid * 66 + w];
        if (tid < 64) atomicAdd(&g_sum_re[n * 64 + tid], s);
        else          atomicAdd(&g_sum_im[n * 64 + (tid - 64)], s);
    }
    // write out: g_xeig[(n,h,w,e)]
    int base = (n * 64 + h) * 4096;
    for (int i = tid; i < 4096; i += 256) {
        int w = i >> 6, e = i & 63;
        g_xeig_re[base + i] = ob[e * 66 + w];
        g_xeig_im[base + i] = ob[(64 + e) * 66 + w];
    }
}

// ---------------- kernel 4a: flux recurrence + a_h/c_h ----------------
__global__ void k_flux1(const float* __restrict__ dtp,
                        const float* __restrict__ lfre, const float* __restrict__ lfim,
                        const float* __restrict__ lhre, const float* __restrict__ lhim,
                        const float* __restrict__ fpre, const float* __restrict__ fpim,
                        float* __restrict__ out) {
    int tid = threadIdx.x;           // 256
    int b = tid >> 6, d = tid & 63;
    float dtv = dtp[0];
    float lfr = -fabsf(lfre[d]), lfi = lfim[d];
    float efac = expf(lfr * dtv);
    float afr = efac * cosf(lfi * dtv), afi = efac * sinf(lfi * dtv);
    float den = lfr * lfr + lfi * lfi;
    float nr = afr - 1.f, ni = afi;
    float cfr = (nr * lfr + ni * lfi) / den;
    float cfi = (ni * lfr - nr * lfi) / den;
    float fr = fpre[b * 64 + d], fi = fpim[b * 64 + d];
    for (int t = 0; t < TT; t++) {
        g_ff_re[(b * TT + t) * 64 + d] = fr;
        g_ff_im[(b * TT + t) * 64 + d] = fi;
        float xmr = g_sum_re[(b * TT + t) * 64 + d] * (1.f / 4096.f);
        float xmi = g_sum_im[(b * TT + t) * 64 + d] * (1.f / 4096.f);
        float ur = xmr * cfr - xmi * cfi;
        float ui = xmr * cfi + xmi * cfr;
        float nfr = afr * fr - afi * fi + ur;
        float nfi = afr * fi + afi * fr + ui;
        fr = nfr; fi = nfi;
    }
    out[FLUX_RE + b * 64 + d] = fr;
    out[FLUX_IM + b * 64 + d] = fi;

    if (tid < 64) {
        float lr = -fabsf(lhre[tid]), li = lhim[tid];
        float e2 = expf(lr * dtv);
        float ahr = e2 * cosf(li * dtv), ahi = e2 * sinf(li * dtv);
        float dd = lr * lr + li * li;
        float mr = ahr - 1.f, mi = ahi;
        g_ah_re[tid] = ahr; g_ah_im[tid] = ahi;
        g_ch_re[tid] = (mr * lr + mi * li) / dd;
        g_ch_im[tid] = (mi * lr - mr * li) / dd;
    }
}

// ---------------- kernel 4b: source & gate ----------------
__global__ void k_flux2(const float* __restrict__ Wsr, const float* __restrict__ Wsi,
                        const float* __restrict__ Wg,  const float* __restrict__ bg) {
    int blk = blockIdx.x;            // 32 = B*T
    int e = threadIdx.x;             // 64
    __shared__ float sfr[64], sfi[64];
    sfr[e] = g_ff_re[blk * 64 + e];
    sfi[e] = g_ff_im[blk * 64 + e];
    __syncthreads();
    float sr = 0.f, si = 0.f, ga = bg[e];
    #pragma unroll 4
    for (int dd = 0; dd < 64; dd++) {
        float ffr = sfr[dd], ffi = sfi[dd];
        float wr = Wsr[dd * 64 + e], wi = Wsi[dd * 64 + e];
        sr += ffr * wr - ffi * wi;
        si += ffr * wi + ffi * wr;
        ga += ffr * Wg[dd * 64 + e];
    }
    int q = blk * 64 + e;
    g_src_re[q] = sr;
    g_src_im[q] = si;
    g_gate[q] = 1.f / (1.f + expf(-ga));
}

// ---------------- kernel 5: T-scan for y + h_out ----------------
__global__ void k_scan(const float* __restrict__ hpr, const float* __restrict__ hpi,
                       float* __restrict__ out) {
    int gid = blockIdx.x * 256 + threadIdx.x;    // 1048576 threads
    int e = gid & 63;
    int pos = gid >> 6;                          // b*4096 + hw
    int b = pos >> 12, hw = pos & 4095;
    float ahr = g_ah_re[e], ahi = g_ah_im[e];
    float chr = g_ch_re[e], chi = g_ch_im[e];
    float yr = hpr[gid], yi = hpi[gid];
    #pragma unroll
    for (int t = 0; t < TT; t++) {
        int idx = ((b * TT + t) * 4096 + hw) * 64 + e;
        float xr = g_xeig_re[idx], xi = g_xeig_im[idx];
        int q = (b * TT + t) * 64 + e;
        float gg = g_gate[q];
        float sr = g_src_re[q], si = g_src_im[q];
        float fr = xr * gg + sr * (1.f - gg);
        float fi = xi * gg + si * (1.f - gg);
        float ur = fr * chr - fi * chi;
        float ui = fr * chi + fi * chr;
        float nyr = ahr * yr - ahi * yi + ur;
        float nyi = ahr * yi + ahi * yr + ui;
        yr = nyr; yi = nyi;
        g_y_re[idx] = yr; g_y_im[idx] = yi;
    }
    out[HOUT_RE + gid] = yr;
    out[HOUT_IM + gid] = yi;
}

// ---------------- kernel 6: y_dec via tf32 mma -> z rows ----------------
// Same GEMM as k_eig with B from Edec; C = [re | im] = exactly the g_z row layout.
__global__ void __launch_bounds__(256) k_dec(const float* __restrict__ Er, const float* __restrict__ Ei) {
    extern __shared__ float sm[];
    float* sA = sm;               // 128 x 65
    float* sB = sm + 128 * 65;    // 128 x 132
    int n = blockIdx.x >> 6, h = blockIdx.x & 63;
    int tid = threadIdx.x;
    int lane = tid & 31, warp = tid >> 5;
    int wm = warp >> 1, wn = warp & 1;
    int rowb = wm * 16;
    int lg = lane >> 2;
    int lt = lane & 3;
    int base = (n * 64 + h) * 4096;

    // stage A: y is (n,h,w,d): consecutive i -> consecutive d: coalesced; write sA[k][w]
    for (int i = tid; i < 4096; i += 256) {
        int w = i >> 6, d = i & 63;
        sA[d * 65 + w]        = g_y_re[base + i];
        sA[(64 + d) * 65 + w] = g_y_im[base + i];
    }
    for (int i = tid; i < 4096; i += 256) {
        int d = i >> 6, e = i & 63;
        float er = Er[d * 64 + e], ei = Ei[d * 64 + e];
        sB[d * 132 + e]              = tf32r(er);
        sB[d * 132 + 64 + e]         = tf32r(ei);
        sB[(64 + d) * 132 + e]       = tf32r(-ei);
        sB[(64 + d) * 132 + 64 + e]  = tf32r(er);
    }
    __syncthreads();

    float c2[8][4];
    #pragma unroll
    for (int a = 0; a < 8; a++)
        #pragma unroll
        for (int q = 0; q < 4; q++) c2[a][q] = 0.f;
    #pragma unroll
    for (int k0 = 0; k0 < 16; k0++) {
        int kb = k0 * 8;
        float a0 = tf32r(sA[(kb + lt) * 65 + rowb + lg]);
        float a1 = tf32r(sA[(kb + lt) * 65 + rowb + lg + 8]);
        float a2 = tf32r(sA[(kb + lt + 4) * 65 + rowb + lg]);
        float a3 = tf32r(sA[(kb + lt + 4) * 65 + rowb + lg + 8]);
        #pragma unroll
        for (int nt = 0; nt < 8; nt++) {
            int nb = wn * 64 + nt * 8;
            float bb0 = sB[(kb + lt) * 132 + nb + lg];
            float bb1 = sB[(kb + lt + 4) * 132 + nb + lg];
            mma_tf32(c2[nt], a0, a1, a2, a3, bb0, bb1);
        }
    }
    __syncthreads();
    float* ob = sB;
    #pragma unroll
    for (int nt = 0; nt < 8; nt++) {
        #pragma unroll
        for (int q = 0; q < 4; q++) {
            int rr = rowb + lg + ((q >= 2) ? 8 : 0);
            int cc = wn * 64 + nt * 8 + lt * 2 + (q & 1);
            ob[cc * 66 + rr] = c2[nt][q];
        }
    }
    __syncthreads();
    int zb = (n * 64 + h) * 8192;
    for (int i = tid; i < 8192; i += 256) {
        int w = i >> 7, c = i & 127;
        g_z[zb + i] = ob[c * 66 + w];
    }
}

// ---------------- kernel 7: fused FFN via tf32 mma.sync + final residual ----------------
__global__ void __launch_bounds__(256) k_ffn(const float* __restrict__ w1, const float* __restrict__ b1,
                                             const float* __restrict__ w2, const float* __restrict__ b2,
                                             float* __restrict__ out) {
    extern __shared__ float sm[];
    float* zs = sm;                   // 64 x 132
    float* wb = zs + 64 * 132;        // 9216 floats
    float* hd = wb + 9216;            // 64 x 72
    int blk = blockIdx.x;             // 2048
    int n = blk >> 6, h = blk & 63;
    int tid = threadIdx.x;
    int lane = tid & 31, warp = tid >> 5;
    int wm = warp >> 1, wn = warp & 1;
    int rowb = wm * 16;
    int lg = lane >> 2;
    int lt = lane & 3;
    int rowbase = (n * 64 + h) * 64;

    for (int i = tid; i < 8192; i += 256)
        zs[(i >> 7) * 132 + (i & 127)] = g_z[(rowbase + (i >> 7)) * 128 + (i & 127)];

    float c2[8][4];
    #pragma unroll
    for (int a = 0; a < 8; a++)
        #pragma unroll
        for (int q = 0; q < 4; q++) c2[a][q] = 0.f;

    for (int hc = 0; hc < 8; hc++) {
        __syncthreads();
        for (int i = tid; i < 8192; i += 256) {
            int k = i >> 6, j = i & 63;
            wb[k * 72 + j] = tf32r(w1[k * 512 + hc * 64 + j]);
        }
        __syncthreads();
        float c1[4][4];
        #pragma unroll
        for (int a = 0; a < 4; a++)
            #pragma unroll
            for (int q = 0; q < 4; q++) c1[a][q] = 0.f;
        for (int k0 = 0; k0 < 16; k0++) {
            int kb = k0 * 8;
            float a0 = tf32r(zs[(rowb + lg) * 132 + kb + lt]);
            float a1 = tf32r(zs[(rowb + lg + 8) * 132 + kb + lt]);
            float a2 = tf32r(zs[(rowb + lg) * 132 + kb + lt + 4]);
            float a3 = tf32r(zs[(rowb + lg + 8) * 132 + kb + lt + 4]);
            #pragma unroll
            for (int nt = 0; nt < 4; nt++) {
                int nb = wn * 32 + nt * 8;
                float bb0 = wb[(kb + lt) * 72 + nb + lg];
                float bb1 = wb[(kb + lt + 4) * 72 + nb + lg];
                mma_tf32(c1[nt], a0, a1, a2, a3, bb0, bb1);
            }
        }
        #pragma unroll
        for (int nt = 0; nt < 4; nt++) {
            #pragma unroll
            for (int q = 0; q < 4; q++) {
                int rr = rowb + lg + ((q >= 2) ? 8 : 0);
                int cc = wn * 32 + nt * 8 + lt * 2 + (q & 1);
                float x = c1[nt][q] + b1[hc * 64 + cc];
                float t = tanhf(0.7978845608028654f * (x + 0.044715f * x * x * x));
                hd[rr * 72 + cc] = tf32r(0.5f * x * (1.f + t));
            }
        }
        __syncthreads();
        for (int i = tid; i < 8192; i += 256) {
            int k = i >> 7, c = i & 127;
            wb[k * 136 + c] = tf32r(w2[(hc * 64 + k) * 128 + c]);
        }
        __syncthreads();
        for (int k0 = 0; k0 < 8; k0++) {
            int kb = k0 * 8;
            float a0 = hd[(rowb + lg) * 72 + kb + lt];
            float a1 = hd[(rowb + lg + 8) * 72 + kb + lt];
            float a2 = hd[(rowb + lg) * 72 + kb + lt + 4];
            float a3 = hd[(rowb + lg + 8) * 72 + kb + lt + 4];
            #pragma unroll
            for (int nt = 0; nt < 8; nt++) {
                int nb = wn * 64 + nt * 8;
                float bb0 = wb[(kb + lt) * 136 + nb + lg];
                float bb1 = wb[(kb + lt + 4) * 136 + nb + lg];
                mma_tf32(c2[nt], a0, a1, a2, a3, bb0, bb1);
            }
        }
    }
    __syncthreads();
    float* ob = wb;
    #pragma unroll
    for (int nt = 0; nt < 8; nt++) {
        #pragma unroll
        for (int q = 0; q < 4; q++) {
            int rr = rowb + lg + ((q >= 2) ? 8 : 0);
            int cc = wn * 64 + nt * 8 + lt * 2 + (q & 1);
            ob[cc * 66 + rr] = c2[nt][q];
        }
    }
    __syncthreads();
    for (int i = tid; i < 8192; i += 256) {
        int c = i >> 6, w = i & 63;
        float o = ob[c * 66 + w] + b2[c];
        float zv = zs[w * 132 + c];
        int d = c & 63;
        int gidx = ((n * 64 + d) * 64 + h) * 64 + w;
        if (c < 64) out[OUT_RE + gidx] = g_xsp_re[gidx] + zv + o;
        else        out[OUT_IM + gidx] = g_xsp_im[gidx] + zv + o;
    }
}

// ---------------- launch ----------------
extern "C" void kernel_launch(void* const* d_in, const int* in_sizes, int n_in,
                              void* d_out, int out_size) {
    const float* x_re      = (const float*)d_in[0];
    const float* x_im      = (const float*)d_in[1];
    const float* h_prev_re = (const float*)d_in[2];
    const float* h_prev_im = (const float*)d_in[3];
    const float* flux_p_re = (const float*)d_in[4];
    const float* flux_p_im = (const float*)d_in[5];
    const float* dt        = (const float*)d_in[6];
    const float* ln_gamma  = (const float*)d_in[7];
    const float* ln_beta   = (const float*)d_in[8];
    const float* conv_w    = (const float*)d_in[9];
    const float* conv_b    = (const float*)d_in[10];
    const float* metric    = (const float*)d_in[11];
    const float* E_re      = (const float*)d_in[12];
    const float* E_im      = (const float*)d_in[13];
    const float* Edec_re   = (const float*)d_in[14];
    const float* Edec_im   = (const float*)d_in[15];
    const float* lam_h_re  = (const float*)d_in[16];
    const float* lam_h_im  = (const float*)d_in[17];
    const float* lam_f_re  = (const float*)d_in[18];
    const float* lam_f_im  = (const float*)d_in[19];
    const float* W_src_re  = (const float*)d_in[20];
    const float* W_src_im  = (const float*)d_in[21];
    const float* W_gate    = (const float*)d_in[22];
    const float* b_gate    = (const float*)d_in[23];
    const float* ffn_w1    = (const float*)d_in[24];
    const float* ffn_b1    = (const float*)d_in[25];
    const float* ffn_w2    = (const float*)d_in[26];
    const float* ffn_b2    = (const float*)d_in[27];
    float* out = (float*)d_out;

    const int smem_ed   = (128 * 65 + 128 * 132) * 4;                      // 100864
    const int smem_ffn  = (64 * 132 + 9216 + 64 * 72) * 4;                 // 89088
    const int smem_conv = (6528 + 4224) * 4;                               // 43008
    cudaFuncSetAttribute(k_eig, cudaFuncAttributeMaxDynamicSharedMemorySize, smem_ed);
    cudaFuncSetAttribute(k_dec, cudaFuncAttributeMaxDynamicSharedMemorySize, smem_ed);
    cudaFuncSetAttribute(k_ffn, cudaFuncAttributeMaxDynamicSharedMemorySize, smem_ffn);
    cudaFuncSetAttribute(k_conv, cudaFuncAttributeMaxDynamicSharedMemorySize, smem_conv);

    k_wtr <<<(9 * 128 * 128 + 255) / 256, 256>>>(conv_w);
    k_ln  <<<NB * HH, 64>>>(x_re, x_im, ln_gamma, ln_beta);
    k_conv<<<NB * HH, 256, smem_conv>>>(x_re, x_im, conv_b, metric);
    k_eig <<<NB * HH, 256, smem_ed>>>(E_re, E_im);
    k_flux1<<<1, 256>>>(dt, lam_f_re, lam_f_im, lam_h_re, lam_h_im,
                        flux_p_re, flux_p_im, out);
    k_flux2<<<32, 64>>>(W_src_re, W_src_im, W_gate, b_gate);
    k_scan<<<4096, 256>>>(h_prev_re, h_prev_im, out);
    k_dec <<<NB * HH, 256, smem_ed>>>(Edec_re, Edec_im);
    k_ffn <<<NB * HH, 256, smem_ffn>>>(ffn_w1, ffn_b1, ffn_w2, ffn_b2, out);
}